// round 1
// baseline (speedup 1.0000x reference)
#include <cuda_runtime.h>
#include <math.h>

// ---------------------------------------------------------------------------
// Problem constants
// ---------------------------------------------------------------------------
#define BATCH   16384
#define FDIM    256
#define NPAIRS  2016
#define K0      (FDIM + NPAIRS)   // 2272
#define D1      2048
#define D2      2048
#define D3      1024
#define BN_EPS  1e-5f

// ---------------------------------------------------------------------------
// Scratch (static __device__ arrays; no runtime allocation allowed)
// ---------------------------------------------------------------------------
__device__ float g_H0[BATCH * (size_t)K0];   // 149 MB  pairwise-augmented input
__device__ float g_Z0[BATCH * (size_t)D1];   // 134 MB  layer0 pre/post act (in-place)
__device__ float g_Z1[BATCH * (size_t)D2];   // 134 MB
__device__ float g_Z2[BATCH * (size_t)D3];   //  67 MB
__device__ float g_PS[64 * D1];              // partial column sums
__device__ float g_PQ[64 * D1];              // partial column sumsq
__device__ float g_SCALE[D1];
__device__ float g_SHIFT[D1];
__device__ int   g_PI[NPAIRS];
__device__ int   g_PJ[NPAIRS];

// ---------------------------------------------------------------------------
// Pair table: row-major upper triangle of 64x64, k=1  (matches np.triu_indices)
// offset(i) = (127*i - i*i)/2
// ---------------------------------------------------------------------------
__global__ void build_pairs_kernel() {
    int p = blockIdx.x * blockDim.x + threadIdx.x;
    if (p >= NPAIRS) return;
    float disc = sqrtf(16129.0f - 8.0f * (float)p);
    int i = (int)((127.0f - disc) * 0.5f);
    // integer fix-up against fp rounding
    while (((127 * (i + 1) - (i + 1) * (i + 1)) >> 1) <= p) i++;
    while (((127 * i - i * i) >> 1) > p) i--;
    int off = (127 * i - i * i) >> 1;
    int j = p - off + i + 1;
    g_PI[p] = i;
    g_PJ[p] = j;
}

// ---------------------------------------------------------------------------
// H0 = concat(xv, xv[:,i]*xv[:,j]/255)   one block per batch row
// ---------------------------------------------------------------------------
__global__ void __launch_bounds__(256) build_h0_kernel(const float* __restrict__ xv) {
    __shared__ float row[FDIM];
    int b = blockIdx.x;
    int tid = threadIdx.x;
    row[tid] = xv[(size_t)b * FDIM + tid];
    __syncthreads();
    float* h = g_H0 + (size_t)b * K0;
    h[tid] = row[tid];
    const float inv255 = 1.0f / 255.0f;
    #pragma unroll
    for (int p = tid; p < NPAIRS; p += 256) {
        h[FDIM + p] = row[g_PI[p]] * row[g_PJ[p]] * inv255;
    }
}

// ---------------------------------------------------------------------------
// SGEMM (NT): C[M,N] = A[M,K] (row-major) * W[N,K]^T (row-major)
// 128x128 block tile, BK=16, 8x8 per thread, 256 threads, padded smem.
// M,N multiples of 128; K multiple of 16; all rows 16B-aligned.
// ---------------------------------------------------------------------------
#define SLDA 132   // padded leading dim (bank-conflict-free transpose stores)

__global__ void __launch_bounds__(256) sgemm_nt_kernel(
    const float* __restrict__ A, const float* __restrict__ W,
    float* __restrict__ C, int M, int N, int K)
{
    __shared__ float As[16 * SLDA];
    __shared__ float Bs[16 * SLDA];

    const int tid = threadIdx.x;
    const int bm = blockIdx.y;
    const int bn = blockIdx.x;

    const float* Ap = A + (size_t)bm * 128 * K;
    const float* Wp = W + (size_t)bn * 128 * K;

    const int loadRow = tid >> 2;          // 0..63
    const int loadCol = (tid & 3) * 4;     // 0,4,8,12

    const int tRow = (tid >> 4) * 8;       // 0..120
    const int tCol = (tid & 15) * 8;       // 0..120

    float acc[8][8];
    #pragma unroll
    for (int m = 0; m < 8; m++)
        #pragma unroll
        for (int n = 0; n < 8; n++) acc[m][n] = 0.0f;

    for (int kt = 0; kt < K; kt += 16) {
        #pragma unroll
        for (int r = 0; r < 128; r += 64) {
            float4 va = *(const float4*)(Ap + (size_t)(loadRow + r) * K + kt + loadCol);
            As[(loadCol + 0) * SLDA + loadRow + r] = va.x;
            As[(loadCol + 1) * SLDA + loadRow + r] = va.y;
            As[(loadCol + 2) * SLDA + loadRow + r] = va.z;
            As[(loadCol + 3) * SLDA + loadRow + r] = va.w;
            float4 vb = *(const float4*)(Wp + (size_t)(loadRow + r) * K + kt + loadCol);
            Bs[(loadCol + 0) * SLDA + loadRow + r] = vb.x;
            Bs[(loadCol + 1) * SLDA + loadRow + r] = vb.y;
            Bs[(loadCol + 2) * SLDA + loadRow + r] = vb.z;
            Bs[(loadCol + 3) * SLDA + loadRow + r] = vb.w;
        }
        __syncthreads();

        #pragma unroll
        for (int k = 0; k < 16; k++) {
            float ra[8], rb[8];
            *(float4*)&ra[0] = *(const float4*)&As[k * SLDA + tRow + 0];
            *(float4*)&ra[4] = *(const float4*)&As[k * SLDA + tRow + 4];
            *(float4*)&rb[0] = *(const float4*)&Bs[k * SLDA + tCol + 0];
            *(float4*)&rb[4] = *(const float4*)&Bs[k * SLDA + tCol + 4];
            #pragma unroll
            for (int m = 0; m < 8; m++)
                #pragma unroll
                for (int n = 0; n < 8; n++)
                    acc[m][n] = fmaf(ra[m], rb[n], acc[m][n]);
        }
        __syncthreads();
    }

    // epilogue
    #pragma unroll
    for (int m = 0; m < 8; m++) {
        float* crow = C + (size_t)(bm * 128 + tRow + m) * N + bn * 128 + tCol;
        float4 v0 = make_float4(acc[m][0], acc[m][1], acc[m][2], acc[m][3]);
        float4 v1 = make_float4(acc[m][4], acc[m][5], acc[m][6], acc[m][7]);
        *(float4*)(crow + 0) = v0;
        *(float4*)(crow + 4) = v1;
    }
}

// ---------------------------------------------------------------------------
// BatchNorm stats, stage 1: partial per-column sum & sumsq over a 256-row chunk
// grid: (D/256, 64), block 256. Deterministic (no atomics).
// ---------------------------------------------------------------------------
__global__ void __launch_bounds__(256) colstats_partial_kernel(
    const float* __restrict__ Z, int D)
{
    int col = blockIdx.x * 256 + threadIdx.x;
    size_t base = (size_t)(blockIdx.y * 256) * D + col;
    float s = 0.0f, q = 0.0f;
    #pragma unroll 4
    for (int r = 0; r < 256; r++) {
        float v = Z[base + (size_t)r * D];
        s += v;
        q = fmaf(v, v, q);
    }
    g_PS[blockIdx.y * D + col] = s;
    g_PQ[blockIdx.y * D + col] = q;
}

// stage 2: reduce 64 partials -> scale/shift per column (fold gamma/beta in)
__global__ void __launch_bounds__(256) bn_finalize_kernel(
    const float* __restrict__ g, const float* __restrict__ be, int D)
{
    int col = blockIdx.x * 256 + threadIdx.x;
    if (col >= D) return;
    float s = 0.0f, q = 0.0f;
    #pragma unroll
    for (int c = 0; c < 64; c++) {
        s += g_PS[c * D + col];
        q += g_PQ[c * D + col];
    }
    float invB = 1.0f / (float)BATCH;
    float mean = s * invB;
    float var  = q * invB - mean * mean;
    float sc   = g[col] / sqrtf(var + BN_EPS);
    g_SCALE[col] = sc;
    g_SHIFT[col] = be[col] - mean * sc;
}

// BN + ReLU, in place, vectorized
__global__ void __launch_bounds__(256) bn_relu_kernel(float* __restrict__ Z, int D, int total4)
{
    int i = blockIdx.x * 256 + threadIdx.x;
    if (i >= total4) return;
    int col = (i * 4) % D;
    float4 v = ((float4*)Z)[i];
    v.x = fmaxf(0.0f, fmaf(v.x, g_SCALE[col + 0], g_SHIFT[col + 0]));
    v.y = fmaxf(0.0f, fmaf(v.y, g_SCALE[col + 1], g_SHIFT[col + 1]));
    v.z = fmaxf(0.0f, fmaf(v.z, g_SCALE[col + 2], g_SHIFT[col + 2]));
    v.w = fmaxf(0.0f, fmaf(v.w, g_SCALE[col + 3], g_SHIFT[col + 3]));
    ((float4*)Z)[i] = v;
}

// ---------------------------------------------------------------------------
// Output GEMV: out[b] = dot(A2[b,:1024], Wout) + bout   (one warp per row)
// ---------------------------------------------------------------------------
__global__ void __launch_bounds__(256) out_gemv_kernel(
    const float* __restrict__ A2, const float* __restrict__ Wout,
    const float* __restrict__ bout, float* __restrict__ out)
{
    __shared__ float w[D3];
    int tid = threadIdx.x;
    ((float4*)w)[tid] = ((const float4*)Wout)[tid];   // 256 * 4 = 1024 floats
    __syncthreads();

    int warp = tid >> 5;
    int lane = tid & 31;
    int b = blockIdx.x * 8 + warp;
    const float* a = A2 + (size_t)b * D3;

    float sum = 0.0f;
    #pragma unroll
    for (int it = 0; it < 8; it++) {
        int k = it * 128 + lane * 4;
        float4 av = *(const float4*)(a + k);
        float4 wv = *(const float4*)(w + k);
        sum = fmaf(av.x, wv.x, sum);
        sum = fmaf(av.y, wv.y, sum);
        sum = fmaf(av.z, wv.z, sum);
        sum = fmaf(av.w, wv.w, sum);
    }
    #pragma unroll
    for (int off = 16; off > 0; off >>= 1)
        sum += __shfl_down_sync(0xFFFFFFFFu, sum, off);
    if (lane == 0) out[b] = sum + bout[0];
}

// ---------------------------------------------------------------------------
// Host launcher.
// Inputs: 0 xv, 1 W0, 2 b0, 3 g0, 4 be0, 5 W1, 6 b1, 7 g1, 8 be1,
//         9 W2, 10 b2, 11 g2, 12 be2, 13 Wout, 14 bout
// NOTE: b0/b1/b2 are mathematically irrelevant (train-mode BN removes any
//       per-column constant), so they are never read.
// ---------------------------------------------------------------------------
extern "C" void kernel_launch(void* const* d_in, const int* in_sizes, int n_in,
                              void* d_out, int out_size)
{
    const float* xv   = (const float*)d_in[0];
    const float* W0   = (const float*)d_in[1];
    const float* g0   = (const float*)d_in[3];
    const float* be0  = (const float*)d_in[4];
    const float* W1   = (const float*)d_in[5];
    const float* g1   = (const float*)d_in[7];
    const float* be1  = (const float*)d_in[8];
    const float* W2   = (const float*)d_in[9];
    const float* g2   = (const float*)d_in[11];
    const float* be2  = (const float*)d_in[12];
    const float* Wout = (const float*)d_in[13];
    const float* bout = (const float*)d_in[14];
    float* out = (float*)d_out;

    float *H0, *Z0, *Z1, *Z2;
    cudaGetSymbolAddress((void**)&H0, g_H0);
    cudaGetSymbolAddress((void**)&Z0, g_Z0);
    cudaGetSymbolAddress((void**)&Z1, g_Z1);
    cudaGetSymbolAddress((void**)&Z2, g_Z2);

    // frontend
    build_pairs_kernel<<<8, 256>>>();
    build_h0_kernel<<<BATCH, 256>>>(xv);

    // layer 0: [B,2272] x [2048,2272]^T
    sgemm_nt_kernel<<<dim3(D1 / 128, BATCH / 128), 256>>>(H0, W0, Z0, BATCH, D1, K0);
    colstats_partial_kernel<<<dim3(D1 / 256, 64), 256>>>(Z0, D1);
    bn_finalize_kernel<<<D1 / 256, 256>>>(g0, be0, D1);
    bn_relu_kernel<<<(BATCH * D1 / 4) / 256, 256>>>(Z0, D1, BATCH * D1 / 4);

    // layer 1: [B,2048] x [2048,2048]^T
    sgemm_nt_kernel<<<dim3(D2 / 128, BATCH / 128), 256>>>(Z0, W1, Z1, BATCH, D2, D1);
    colstats_partial_kernel<<<dim3(D2 / 256, 64), 256>>>(Z1, D2);
    bn_finalize_kernel<<<D2 / 256, 256>>>(g1, be1, D2);
    bn_relu_kernel<<<(BATCH * D2 / 4) / 256, 256>>>(Z1, D2, BATCH * D2 / 4);

    // layer 2: [B,2048] x [1024,2048]^T
    sgemm_nt_kernel<<<dim3(D3 / 128, BATCH / 128), 256>>>(Z1, W2, Z2, BATCH, D3, D2);
    colstats_partial_kernel<<<dim3(D3 / 256, 64), 256>>>(Z2, D3);
    bn_finalize_kernel<<<D3 / 256, 256>>>(g2, be2, D3);
    bn_relu_kernel<<<(BATCH * D3 / 4) / 256, 256>>>(Z2, D3, BATCH * D3 / 4);

    // output head
    out_gemv_kernel<<<BATCH / 8, 256>>>(Z2, Wout, bout, out);
}

// round 3
// speedup vs baseline: 3.1026x; 3.1026x over previous
#include <cuda_runtime.h>
#include <cuda_bf16.h>
#include <cstdint>
#include <math.h>

// ---------------------------------------------------------------------------
// Problem constants
// ---------------------------------------------------------------------------
#define BATCH   16384
#define FDIM    256
#define NPAIRS  2016
#define K0      2272
#define K0P     2304          // padded to multiple of 64
#define D1      2048
#define D2      2048
#define D3      1024
#define BN_EPS  1e-5f

// ---------------------------------------------------------------------------
// Scratch (static device arrays; runtime allocation forbidden)
// ---------------------------------------------------------------------------
__device__ __nv_bfloat16 g_H0h[BATCH * (size_t)K0P];
__device__ __nv_bfloat16 g_H0l[BATCH * (size_t)K0P];
__device__ __nv_bfloat16 g_Ah [BATCH * (size_t)D1];
__device__ __nv_bfloat16 g_Al [BATCH * (size_t)D1];
__device__ float         g_Z  [BATCH * (size_t)D1];
__device__ __nv_bfloat16 g_W0h[(size_t)D1 * K0P], g_W0l[(size_t)D1 * K0P];
__device__ __nv_bfloat16 g_W1h[(size_t)D2 * D1],  g_W1l[(size_t)D2 * D1];
__device__ __nv_bfloat16 g_W2h[(size_t)D3 * D2],  g_W2l[(size_t)D3 * D2];
__device__ float g_PS[64 * D1];
__device__ float g_PQ[64 * D1];
__device__ float g_SCALE[D1];
__device__ float g_SHIFT[D1];
__device__ int   g_PI[NPAIRS];
__device__ int   g_PJ[NPAIRS];

__device__ __forceinline__ void split2(float x, __nv_bfloat16& h, __nv_bfloat16& l) {
    h = __float2bfloat16_rn(x);
    l = __float2bfloat16_rn(x - __bfloat162float(h));
}

// ---------------------------------------------------------------------------
// PTX wrappers (all plain sm_80+ features; no tcgen05)
// ---------------------------------------------------------------------------
__device__ __forceinline__ uint32_t smem_u32(const void* p) {
    uint32_t a;
    asm("{ .reg .u64 t; cvta.to.shared.u64 t, %1; cvt.u32.u64 %0, t; }" : "=r"(a) : "l"(p));
    return a;
}
__device__ __forceinline__ void cp16(uint32_t saddr, const void* gaddr) {
    asm volatile("cp.async.cg.shared.global [%0], [%1], 16;" :: "r"(saddr), "l"(gaddr));
}
__device__ __forceinline__ void ldsm_x4(uint32_t (&r)[4], uint32_t addr) {
    asm volatile("ldmatrix.sync.aligned.m8n8.x4.shared.b16 {%0,%1,%2,%3}, [%4];"
        : "=r"(r[0]), "=r"(r[1]), "=r"(r[2]), "=r"(r[3]) : "r"(addr));
}
__device__ __forceinline__ void mma16816(float (&d)[4], const uint32_t (&a)[4],
                                         uint32_t b0, uint32_t b1) {
    asm volatile(
        "mma.sync.aligned.m16n8k16.row.col.f32.bf16.bf16.f32 "
        "{%0,%1,%2,%3}, {%4,%5,%6,%7}, {%8,%9}, {%0,%1,%2,%3};"
        : "+f"(d[0]), "+f"(d[1]), "+f"(d[2]), "+f"(d[3])
        : "r"(a[0]), "r"(a[1]), "r"(a[2]), "r"(a[3]), "r"(b0), "r"(b1));
}

// ---------------------------------------------------------------------------
// Pair table (row-major upper triangle, k=1)
// ---------------------------------------------------------------------------
__global__ void build_pairs_kernel() {
    int p = blockIdx.x * blockDim.x + threadIdx.x;
    if (p >= NPAIRS) return;
    float disc = sqrtf(16129.0f - 8.0f * (float)p);
    int i = (int)((127.0f - disc) * 0.5f);
    while (((127 * (i + 1) - (i + 1) * (i + 1)) >> 1) <= p) i++;
    while (((127 * i - i * i) >> 1) > p) i--;
    int off = (127 * i - i * i) >> 1;
    g_PI[p] = i;
    g_PJ[p] = p - off + i + 1;
}

// ---------------------------------------------------------------------------
// H0 (hi/lo bf16, zero-padded to K0P) — one block per batch row
// ---------------------------------------------------------------------------
__global__ void __launch_bounds__(256) build_h0_kernel(const float* __restrict__ xv) {
    __shared__ float row[FDIM];
    int b = blockIdx.x;
    int tid = threadIdx.x;
    row[tid] = xv[(size_t)b * FDIM + tid];
    __syncthreads();
    __nv_bfloat16* hh = g_H0h + (size_t)b * K0P;
    __nv_bfloat16* hl = g_H0l + (size_t)b * K0P;
    split2(row[tid], hh[tid], hl[tid]);
    const float inv255 = 1.0f / 255.0f;
    for (int p = tid; p < NPAIRS; p += 256) {
        float q = row[g_PI[p]] * row[g_PJ[p]] * inv255;
        split2(q, hh[FDIM + p], hl[FDIM + p]);
    }
    if (tid < K0P - K0) {
        hh[K0 + tid] = __float2bfloat16_rn(0.0f);
        hl[K0 + tid] = __float2bfloat16_rn(0.0f);
    }
}

// ---------------------------------------------------------------------------
// Weight split/pad: W fp32 [N, Kin] -> Wh/Wl bf16 [N, Kout] (zero pad tail)
// ---------------------------------------------------------------------------
__global__ void __launch_bounds__(256) split_w_kernel(
    const float* __restrict__ W, __nv_bfloat16* __restrict__ Wh, __nv_bfloat16* __restrict__ Wl,
    int N, int Kin, int Kout)
{
    size_t idx = (size_t)blockIdx.x * 256 + threadIdx.x;
    size_t total = (size_t)N * Kout;
    if (idx >= total) return;
    int k = (int)(idx % Kout);
    int n = (int)(idx / Kout);
    float x = (k < Kin) ? W[(size_t)n * Kin + k] : 0.0f;
    split2(x, Wh[idx], Wl[idx]);
}

// ---------------------------------------------------------------------------
// mma.sync split-bf16 GEMM: C[M,N] fp32 = (Ah+Al)[M,K] @ (Bh+Bl)[N,K]^T
// CTA 128x128, BK=64, 8 warps (2M x 4N), 3-stage cp.async pipeline.
// Smem per stage: Ah|Al|Bh|Bl, each 128 rows x 128B, SW128 swizzle. 192 KB.
// ---------------------------------------------------------------------------
#define TILE_B  16384u
#define STAGE_B (4u * TILE_B)       // 65536
#define GEMM_SMEM (3u * STAGE_B)    // 196608

__device__ __forceinline__ void load_stage(
    uint32_t sbase, const __nv_bfloat16* __restrict__ ah, const __nv_bfloat16* __restrict__ al,
    const __nv_bfloat16* __restrict__ bh, const __nv_bfloat16* __restrict__ bl,
    int kt, int K, int tid)
{
    const __nv_bfloat16* src[4] = { ah, al, bh, bl };
    #pragma unroll
    for (int t = 0; t < 4; t++) {
        const __nv_bfloat16* g = src[t] + (size_t)kt * 64;
        uint32_t dst = sbase + (uint32_t)t * TILE_B;
        #pragma unroll
        for (int i = 0; i < 4; i++) {
            int idx = tid + i * 256;        // 0..1023
            int row = idx >> 3;
            int ch  = idx & 7;
            uint32_t off = (uint32_t)(row << 7) + (((uint32_t)ch << 4) ^ (((uint32_t)row & 7u) << 4));
            cp16(dst + off, g + (size_t)row * K + (ch << 3));
        }
    }
}

__global__ void __launch_bounds__(256, 1) gemm_bf16x3_kernel(
    const __nv_bfloat16* __restrict__ Ah, const __nv_bfloat16* __restrict__ Al,
    const __nv_bfloat16* __restrict__ Bh, const __nv_bfloat16* __restrict__ Bl,
    float* __restrict__ C, int M, int N, int K)
{
    extern __shared__ char smraw[];
    const uint32_t smb = smem_u32(smraw);
    const int tid  = threadIdx.x;
    const int wid  = tid >> 5;
    const int lane = tid & 31;
    const int wm = wid & 1;            // 0..1  (M dir, 64 rows each)
    const int wn = wid >> 1;           // 0..3  (N dir, 32 cols each)
    const int bn = blockIdx.x, bm = blockIdx.y;
    const int T = K >> 6;

    const __nv_bfloat16* ah = Ah + (size_t)bm * 128 * K;
    const __nv_bfloat16* al = Al + (size_t)bm * 128 * K;
    const __nv_bfloat16* bh = Bh + (size_t)bn * 128 * K;
    const __nv_bfloat16* bl = Bl + (size_t)bn * 128 * K;

    float acc[4][4][4];
    #pragma unroll
    for (int a = 0; a < 4; a++)
        #pragma unroll
        for (int b = 0; b < 4; b++)
            #pragma unroll
            for (int c = 0; c < 4; c++) acc[a][b][c] = 0.0f;

    // per-lane fragment offset precompute (swizzled)
    // A frag: row = wm*64 + mf*16 + (lane&7) + ((lane>>3)&1)*8 ; kbyte = kc*32 + ((lane>>4)&1)*16
    const int aRowBase = wm * 64 + (lane & 7) + ((lane >> 3) & 1) * 8;
    const uint32_t aKsel = ((lane >> 4) & 1) * 16;
    // B frag: row(n) = wn*32 + nb*16 + ((lane>>4)&1)*8 + (lane&7) ; kbyte = kc*32 + ((lane>>3)&1)*16
    const int bRowBase = wn * 32 + ((lane >> 4) & 1) * 8 + (lane & 7);
    const uint32_t bKsel = ((lane >> 3) & 1) * 16;

    // prologue: stages 0 and 1
    load_stage(smb + 0 * STAGE_B, ah, al, bh, bl, 0, K, tid);
    asm volatile("cp.async.commit_group;" ::: "memory");
    load_stage(smb + 1 * STAGE_B, ah, al, bh, bl, 1, K, tid);
    asm volatile("cp.async.commit_group;" ::: "memory");

    int buf = 0;
    for (int kt = 0; kt < T; kt++) {
        if (kt + 2 < T) asm volatile("cp.async.wait_group 1;" ::: "memory");
        else            asm volatile("cp.async.wait_group 0;" ::: "memory");
        __syncthreads();

        if (kt + 2 < T) {
            int nb = kt + 2 - 3 * ((kt + 2) / 3);
            load_stage(smb + (uint32_t)nb * STAGE_B, ah, al, bh, bl, kt + 2, K, tid);
            asm volatile("cp.async.commit_group;" ::: "memory");
        }

        const uint32_t sAh = smb + (uint32_t)buf * STAGE_B;
        const uint32_t sAl = sAh + TILE_B;
        const uint32_t sBh = sAh + 2 * TILE_B;
        const uint32_t sBl = sAh + 3 * TILE_B;

        #pragma unroll
        for (int kc = 0; kc < 4; kc++) {
            uint32_t fah[4][4], fal[4][4];
            #pragma unroll
            for (int mf = 0; mf < 4; mf++) {
                int row = aRowBase + mf * 16;
                uint32_t kb = (uint32_t)kc * 32 + aKsel;
                uint32_t off = ((uint32_t)row << 7) + (kb ^ (((uint32_t)row & 7u) << 4));
                ldsm_x4(fah[mf], sAh + off);
                ldsm_x4(fal[mf], sAl + off);
            }
            uint32_t fbh[2][4], fbl[2][4];
            #pragma unroll
            for (int nb2 = 0; nb2 < 2; nb2++) {
                int row = bRowBase + nb2 * 16;
                uint32_t kb = (uint32_t)kc * 32 + bKsel;
                uint32_t off = ((uint32_t)row << 7) + (kb ^ (((uint32_t)row & 7u) << 4));
                ldsm_x4(fbh[nb2], sBh + off);
                ldsm_x4(fbl[nb2], sBl + off);
            }
            #pragma unroll
            for (int mf = 0; mf < 4; mf++) {
                #pragma unroll
                for (int nf = 0; nf < 4; nf++) {
                    const int g = nf >> 1, h = (nf & 1) * 2;
                    mma16816(acc[mf][nf], fah[mf], fbh[g][h], fbh[g][h + 1]);
                    mma16816(acc[mf][nf], fah[mf], fbl[g][h], fbl[g][h + 1]);
                    mma16816(acc[mf][nf], fal[mf], fbh[g][h], fbh[g][h + 1]);
                }
            }
        }
        buf++;
        if (buf == 3) buf = 0;
        __syncthreads();
    }

    // epilogue
    const int r0 = bm * 128 + wm * 64 + (lane >> 2);
    const int c0 = bn * 128 + wn * 32 + (lane & 3) * 2;
    #pragma unroll
    for (int mf = 0; mf < 4; mf++) {
        #pragma unroll
        for (int nf = 0; nf < 4; nf++) {
            float* p0 = C + (size_t)(r0 + mf * 16) * N + c0 + nf * 8;
            float* p1 = C + (size_t)(r0 + mf * 16 + 8) * N + c0 + nf * 8;
            *(float2*)p0 = make_float2(acc[mf][nf][0], acc[mf][nf][1]);
            *(float2*)p1 = make_float2(acc[mf][nf][2], acc[mf][nf][3]);
        }
    }
}

// ---------------------------------------------------------------------------
// BN stats (deterministic two-stage)
// ---------------------------------------------------------------------------
__global__ void __launch_bounds__(256) colstats_partial_kernel(const float* __restrict__ Z, int D)
{
    int col = blockIdx.x * 256 + threadIdx.x;
    size_t base = (size_t)(blockIdx.y * 256) * D + col;
    float s = 0.0f, q = 0.0f;
    #pragma unroll 4
    for (int r = 0; r < 256; r++) {
        float v = Z[base + (size_t)r * D];
        s += v;
        q = fmaf(v, v, q);
    }
    g_PS[blockIdx.y * D + col] = s;
    g_PQ[blockIdx.y * D + col] = q;
}

__global__ void __launch_bounds__(256) bn_finalize_kernel(
    const float* __restrict__ g, const float* __restrict__ be, int D)
{
    int col = blockIdx.x * 256 + threadIdx.x;
    if (col >= D) return;
    float s = 0.0f, q = 0.0f;
    #pragma unroll
    for (int c = 0; c < 64; c++) { s += g_PS[c * D + col]; q += g_PQ[c * D + col]; }
    float invB = 1.0f / (float)BATCH;
    float mean = s * invB;
    float var  = q * invB - mean * mean;
    float sc   = g[col] / sqrtf(var + BN_EPS);
    g_SCALE[col] = sc;
    g_SHIFT[col] = be[col] - mean * sc;
}

// BN+ReLU -> bf16 hi/lo split (feeds next GEMM)
__global__ void __launch_bounds__(256) bn_relu_split_kernel(
    const float* __restrict__ Z, __nv_bfloat16* __restrict__ Ah, __nv_bfloat16* __restrict__ Al,
    int D, int total4)
{
    int i = blockIdx.x * 256 + threadIdx.x;
    if (i >= total4) return;
    int col = (i * 4) % D;
    float4 v = ((const float4*)Z)[i];
    float y0 = fmaxf(0.0f, fmaf(v.x, g_SCALE[col + 0], g_SHIFT[col + 0]));
    float y1 = fmaxf(0.0f, fmaf(v.y, g_SCALE[col + 1], g_SHIFT[col + 1]));
    float y2 = fmaxf(0.0f, fmaf(v.z, g_SCALE[col + 2], g_SHIFT[col + 2]));
    float y3 = fmaxf(0.0f, fmaf(v.w, g_SCALE[col + 3], g_SHIFT[col + 3]));
    __nv_bfloat16 h0, l0, h1, l1, h2, l2, h3, l3;
    split2(y0, h0, l0); split2(y1, h1, l1); split2(y2, h2, l2); split2(y3, h3, l3);
    ((__nv_bfloat162*)Ah)[i * 2 + 0] = __nv_bfloat162(h0, h1);
    ((__nv_bfloat162*)Ah)[i * 2 + 1] = __nv_bfloat162(h2, h3);
    ((__nv_bfloat162*)Al)[i * 2 + 0] = __nv_bfloat162(l0, l1);
    ((__nv_bfloat162*)Al)[i * 2 + 1] = __nv_bfloat162(l2, l3);
}

// BN+ReLU in place (fp32, for layer 2 -> GEMV)
__global__ void __launch_bounds__(256) bn_relu_kernel(float* __restrict__ Z, int D, int total4)
{
    int i = blockIdx.x * 256 + threadIdx.x;
    if (i >= total4) return;
    int col = (i * 4) % D;
    float4 v = ((float4*)Z)[i];
    v.x = fmaxf(0.0f, fmaf(v.x, g_SCALE[col + 0], g_SHIFT[col + 0]));
    v.y = fmaxf(0.0f, fmaf(v.y, g_SCALE[col + 1], g_SHIFT[col + 1]));
    v.z = fmaxf(0.0f, fmaf(v.z, g_SCALE[col + 2], g_SHIFT[col + 2]));
    v.w = fmaxf(0.0f, fmaf(v.w, g_SCALE[col + 3], g_SHIFT[col + 3]));
    ((float4*)Z)[i] = v;
}

// ---------------------------------------------------------------------------
// Output GEMV: out[b] = dot(Z2[b,:1024], Wout) + bout
// ---------------------------------------------------------------------------
__global__ void __launch_bounds__(256) out_gemv_kernel(
    const float* __restrict__ A2, const float* __restrict__ Wout,
    const float* __restrict__ bout, float* __restrict__ out)
{
    __shared__ float w[D3];
    int tid = threadIdx.x;
    ((float4*)w)[tid] = ((const float4*)Wout)[tid];
    __syncthreads();
    int warp = tid >> 5, lane = tid & 31;
    int b = blockIdx.x * 8 + warp;
    const float* a = A2 + (size_t)b * D3;
    float sum = 0.0f;
    #pragma unroll
    for (int it = 0; it < 8; it++) {
        int k = it * 128 + lane * 4;
        float4 av = *(const float4*)(a + k);
        float4 wv = *(const float4*)(w + k);
        sum = fmaf(av.x, wv.x, sum);
        sum = fmaf(av.y, wv.y, sum);
        sum = fmaf(av.z, wv.z, sum);
        sum = fmaf(av.w, wv.w, sum);
    }
    #pragma unroll
    for (int off = 16; off > 0; off >>= 1) sum += __shfl_down_sync(0xFFFFFFFFu, sum, off);
    if (lane == 0) out[b] = sum + bout[0];
}

// ---------------------------------------------------------------------------
// Host launcher. Inputs: 0 xv, 1 W0, 2 b0, 3 g0, 4 be0, 5 W1, 6 b1, 7 g1,
// 8 be1, 9 W2, 10 b2, 11 g2, 12 be2, 13 Wout, 14 bout.
// b0/b1/b2 are absorbed by train-mode BatchNorm and never read.
// ---------------------------------------------------------------------------
extern "C" void kernel_launch(void* const* d_in, const int* in_sizes, int n_in,
                              void* d_out, int out_size)
{
    const float* xv   = (const float*)d_in[0];
    const float* W0   = (const float*)d_in[1];
    const float* g0   = (const float*)d_in[3];
    const float* be0  = (const float*)d_in[4];
    const float* W1   = (const float*)d_in[5];
    const float* g1   = (const float*)d_in[7];
    const float* be1  = (const float*)d_in[8];
    const float* W2   = (const float*)d_in[9];
    const float* g2   = (const float*)d_in[11];
    const float* be2  = (const float*)d_in[12];
    const float* Wout = (const float*)d_in[13];
    const float* bout = (const float*)d_in[14];
    float* out = (float*)d_out;

    cudaFuncSetAttribute(gemm_bf16x3_kernel, cudaFuncAttributeMaxDynamicSharedMemorySize, GEMM_SMEM);

    __nv_bfloat16 *H0h, *H0l, *Ahp, *Alp, *W0h, *W0l, *W1h, *W1l, *W2h, *W2l;
    float *Z;
    cudaGetSymbolAddress((void**)&H0h, g_H0h);
    cudaGetSymbolAddress((void**)&H0l, g_H0l);
    cudaGetSymbolAddress((void**)&Ahp, g_Ah);
    cudaGetSymbolAddress((void**)&Alp, g_Al);
    cudaGetSymbolAddress((void**)&Z,   g_Z);
    cudaGetSymbolAddress((void**)&W0h, g_W0h);
    cudaGetSymbolAddress((void**)&W0l, g_W0l);
    cudaGetSymbolAddress((void**)&W1h, g_W1h);
    cudaGetSymbolAddress((void**)&W1l, g_W1l);
    cudaGetSymbolAddress((void**)&W2h, g_W2h);
    cudaGetSymbolAddress((void**)&W2l, g_W2l);

    // frontend + weight prep
    build_pairs_kernel<<<8, 256>>>();
    build_h0_kernel<<<BATCH, 256>>>(xv);
    split_w_kernel<<<(int)(((size_t)D1 * K0P + 255) / 256), 256>>>(W0, W0h, W0l, D1, K0, K0P);
    split_w_kernel<<<(int)(((size_t)D2 * D1 + 255) / 256), 256>>>(W1, W1h, W1l, D2, D1, D1);
    split_w_kernel<<<(int)(((size_t)D3 * D2 + 255) / 256), 256>>>(W2, W2h, W2l, D3, D2, D2);

    // layer 0: Z = H0 @ W0^T   [16384, 2048], K = 2304
    gemm_bf16x3_kernel<<<dim3(D1 / 128, BATCH / 128), 256, GEMM_SMEM>>>(H0h, H0l, W0h, W0l, Z, BATCH, D1, K0P);
    colstats_partial_kernel<<<dim3(D1 / 256, 64), 256>>>(Z, D1);
    bn_finalize_kernel<<<D1 / 256, 256>>>(g0, be0, D1);
    bn_relu_split_kernel<<<(BATCH * D1 / 4) / 256, 256>>>(Z, Ahp, Alp, D1, BATCH * D1 / 4);

    // layer 1: Z = A @ W1^T    [16384, 2048], K = 2048
    gemm_bf16x3_kernel<<<dim3(D2 / 128, BATCH / 128), 256, GEMM_SMEM>>>(Ahp, Alp, W1h, W1l, Z, BATCH, D2, D1);
    colstats_partial_kernel<<<dim3(D2 / 256, 64), 256>>>(Z, D2);
    bn_finalize_kernel<<<D2 / 256, 256>>>(g1, be1, D2);
    bn_relu_split_kernel<<<(BATCH * D2 / 4) / 256, 256>>>(Z, Ahp, Alp, D2, BATCH * D2 / 4);

    // layer 2: Z = A @ W2^T    [16384, 1024], K = 2048
    gemm_bf16x3_kernel<<<dim3(D3 / 128, BATCH / 128), 256, GEMM_SMEM>>>(Ahp, Alp, W2h, W2l, Z, BATCH, D3, D2);
    colstats_partial_kernel<<<dim3(D3 / 256, 64), 256>>>(Z, D3);
    bn_finalize_kernel<<<D3 / 256, 256>>>(g2, be2, D3);
    bn_relu_kernel<<<(BATCH * D3 / 4) / 256, 256>>>(Z, D3, BATCH * D3 / 4);

    // output head
    out_gemv_kernel<<<BATCH / 8, 256>>>(Z, Wout, bout, out);
}

// round 4
// speedup vs baseline: 3.1597x; 1.0184x over previous
#include <cuda_runtime.h>
#include <cuda_bf16.h>
#include <cstdint>
#include <math.h>

// ---------------------------------------------------------------------------
// Problem constants
// ---------------------------------------------------------------------------
#define BATCH   16384
#define FDIM    256
#define NPAIRS  2016
#define K0      2272
#define K0P     2304          // padded to multiple of 64
#define D1      2048
#define D2      2048
#define D3      1024
#define BN_EPS  1e-5f

// ---------------------------------------------------------------------------
// Scratch (static device arrays; runtime allocation forbidden)
// ---------------------------------------------------------------------------
__device__ __nv_bfloat16 g_H0h[BATCH * (size_t)K0P];
__device__ __nv_bfloat16 g_H0l[BATCH * (size_t)K0P];
__device__ __nv_bfloat16 g_Ah [BATCH * (size_t)D1];
__device__ __nv_bfloat16 g_Al [BATCH * (size_t)D1];
__device__ float         g_Z  [BATCH * (size_t)D1];
__device__ __nv_bfloat16 g_W0h[(size_t)D1 * K0P], g_W0l[(size_t)D1 * K0P];
__device__ __nv_bfloat16 g_W1h[(size_t)D2 * D1],  g_W1l[(size_t)D2 * D1];
__device__ __nv_bfloat16 g_W2h[(size_t)D3 * D2],  g_W2l[(size_t)D3 * D2];
__device__ float g_PS[64 * D1];
__device__ float g_PQ[64 * D1];
__device__ float g_SCALE[D1];
__device__ float g_SHIFT[D1];
__device__ int   g_PI[NPAIRS];
__device__ int   g_PJ[NPAIRS];

__device__ __forceinline__ void split2(float x, __nv_bfloat16& h, __nv_bfloat16& l) {
    h = __float2bfloat16_rn(x);
    l = __float2bfloat16_rn(x - __bfloat162float(h));
}

// ---------------------------------------------------------------------------
// PTX wrappers (plain sm_80+ features)
// ---------------------------------------------------------------------------
__device__ __forceinline__ uint32_t smem_u32(const void* p) {
    uint32_t a;
    asm("{ .reg .u64 t; cvta.to.shared.u64 t, %1; cvt.u32.u64 %0, t; }" : "=r"(a) : "l"(p));
    return a;
}
__device__ __forceinline__ void cp16(uint32_t saddr, const void* gaddr) {
    asm volatile("cp.async.cg.shared.global [%0], [%1], 16;" :: "r"(saddr), "l"(gaddr));
}
__device__ __forceinline__ void ldsm_x4(uint32_t (&r)[4], uint32_t addr) {
    asm volatile("ldmatrix.sync.aligned.m8n8.x4.shared.b16 {%0,%1,%2,%3}, [%4];"
        : "=r"(r[0]), "=r"(r[1]), "=r"(r[2]), "=r"(r[3]) : "r"(addr));
}
__device__ __forceinline__ void mma16816(float (&d)[4], const uint32_t (&a)[4],
                                         uint32_t b0, uint32_t b1) {
    asm volatile(
        "mma.sync.aligned.m16n8k16.row.col.f32.bf16.bf16.f32 "
        "{%0,%1,%2,%3}, {%4,%5,%6,%7}, {%8,%9}, {%0,%1,%2,%3};"
        : "+f"(d[0]), "+f"(d[1]), "+f"(d[2]), "+f"(d[3])
        : "r"(a[0]), "r"(a[1]), "r"(a[2]), "r"(a[3]), "r"(b0), "r"(b1));
}

// ---------------------------------------------------------------------------
// Pair table (row-major upper triangle, k=1)
// ---------------------------------------------------------------------------
__global__ void build_pairs_kernel() {
    int p = blockIdx.x * blockDim.x + threadIdx.x;
    if (p >= NPAIRS) return;
    float disc = sqrtf(16129.0f - 8.0f * (float)p);
    int i = (int)((127.0f - disc) * 0.5f);
    while (((127 * (i + 1) - (i + 1) * (i + 1)) >> 1) <= p) i++;
    while (((127 * i - i * i) >> 1) > p) i--;
    int off = (127 * i - i * i) >> 1;
    g_PI[p] = i;
    g_PJ[p] = p - off + i + 1;
}

// ---------------------------------------------------------------------------
// H0 (hi/lo bf16, zero-padded to K0P) — one block per batch row
// ---------------------------------------------------------------------------
__global__ void __launch_bounds__(256) build_h0_kernel(const float* __restrict__ xv) {
    __shared__ float row[FDIM];
    int b = blockIdx.x;
    int tid = threadIdx.x;
    row[tid] = xv[(size_t)b * FDIM + tid];
    __syncthreads();
    __nv_bfloat16* hh = g_H0h + (size_t)b * K0P;
    __nv_bfloat16* hl = g_H0l + (size_t)b * K0P;
    split2(row[tid], hh[tid], hl[tid]);
    const float inv255 = 1.0f / 255.0f;
    for (int p = tid; p < NPAIRS; p += 256) {
        float q = row[g_PI[p]] * row[g_PJ[p]] * inv255;
        split2(q, hh[FDIM + p], hl[FDIM + p]);
    }
    if (tid < K0P - K0) {
        hh[K0 + tid] = __float2bfloat16_rn(0.0f);
        hl[K0 + tid] = __float2bfloat16_rn(0.0f);
    }
}

// ---------------------------------------------------------------------------
// Weight split/pad: W fp32 [N, Kin] -> Wh/Wl bf16 [N, Kout] (zero pad tail)
// ---------------------------------------------------------------------------
__global__ void __launch_bounds__(256) split_w_kernel(
    const float* __restrict__ W, __nv_bfloat16* __restrict__ Wh, __nv_bfloat16* __restrict__ Wl,
    int N, int Kin, int Kout)
{
    size_t idx = (size_t)blockIdx.x * 256 + threadIdx.x;
    size_t total = (size_t)N * Kout;
    if (idx >= total) return;
    int k = (int)(idx % Kout);
    int n = (int)(idx / Kout);
    float x = (k < Kin) ? W[(size_t)n * Kin + k] : 0.0f;
    split2(x, Wh[idx], Wl[idx]);
}

// ---------------------------------------------------------------------------
// mma.sync split-bf16 GEMM: C[M,N] fp32 = (Ah+Al)[M,K] @ (Bh+Bl)[N,K]^T
// CTA 256x128, BK=64, 8 warps (4M x 2N), warp tile 64x64, 2-stage cp.async.
// Stage layout: Ah(32K) | Al(32K) | Bh(16K) | Bl(16K) = 96KB; 2 stages = 192KB.
// SW128 swizzle (128B rows), ldmatrix fragments.
// M mult of 256; N mult of 128; K mult of 64.
// ---------------------------------------------------------------------------
#define A_TILE_B 32768u
#define B_TILE_B 16384u
#define STAGE_B  (2u * A_TILE_B + 2u * B_TILE_B)   // 98304
#define GEMM_SMEM (2u * STAGE_B)                   // 196608

__device__ __forceinline__ void load_stage(
    uint32_t sbase, const __nv_bfloat16* __restrict__ ah, const __nv_bfloat16* __restrict__ al,
    const __nv_bfloat16* __restrict__ bh, const __nv_bfloat16* __restrict__ bl,
    int kt, int K, int tid)
{
    // A tiles: 256 rows x 128B (2048 16B-chunks); B tiles: 128 rows (1024 chunks)
    const __nv_bfloat16* ga_h = ah + (size_t)kt * 64;
    const __nv_bfloat16* ga_l = al + (size_t)kt * 64;
    #pragma unroll
    for (int i = 0; i < 8; i++) {
        int idx = tid + i * 256;
        int row = idx >> 3;
        int ch  = idx & 7;
        uint32_t off = (uint32_t)(row << 7) + (((uint32_t)ch << 4) ^ (((uint32_t)row & 7u) << 4));
        size_t goff = (size_t)row * K + (ch << 3);
        cp16(sbase + off, ga_h + goff);
        cp16(sbase + A_TILE_B + off, ga_l + goff);
    }
    const __nv_bfloat16* gb_h = bh + (size_t)kt * 64;
    const __nv_bfloat16* gb_l = bl + (size_t)kt * 64;
    #pragma unroll
    for (int i = 0; i < 4; i++) {
        int idx = tid + i * 256;
        int row = idx >> 3;
        int ch  = idx & 7;
        uint32_t off = (uint32_t)(row << 7) + (((uint32_t)ch << 4) ^ (((uint32_t)row & 7u) << 4));
        size_t goff = (size_t)row * K + (ch << 3);
        cp16(sbase + 2u * A_TILE_B + off, gb_h + goff);
        cp16(sbase + 2u * A_TILE_B + B_TILE_B + off, gb_l + goff);
    }
}

__global__ void __launch_bounds__(256, 1) gemm_bf16x3_kernel(
    const __nv_bfloat16* __restrict__ Ah, const __nv_bfloat16* __restrict__ Al,
    const __nv_bfloat16* __restrict__ Bh, const __nv_bfloat16* __restrict__ Bl,
    float* __restrict__ C, int M, int N, int K)
{
    extern __shared__ char smraw[];
    const uint32_t smb = smem_u32(smraw);
    const int tid  = threadIdx.x;
    const int wid  = tid >> 5;
    const int lane = tid & 31;
    const int wm = wid & 3;            // 0..3  (M dir, 64 rows each)
    const int wn = wid >> 2;           // 0..1  (N dir, 64 cols each)
    const int bn = blockIdx.x, bm = blockIdx.y;
    const int T = K >> 6;

    const __nv_bfloat16* ah = Ah + (size_t)bm * 256 * K;
    const __nv_bfloat16* al = Al + (size_t)bm * 256 * K;
    const __nv_bfloat16* bh = Bh + (size_t)bn * 128 * K;
    const __nv_bfloat16* bl = Bl + (size_t)bn * 128 * K;

    float acc[4][8][4];
    #pragma unroll
    for (int a = 0; a < 4; a++)
        #pragma unroll
        for (int b = 0; b < 8; b++)
            #pragma unroll
            for (int c = 0; c < 4; c++) acc[a][b][c] = 0.0f;

    // A frag: row = wm*64 + mf*16 + (lane&7) + ((lane>>3)&1)*8 ; kbyte = kc*32 + aKsel
    const int aRowBase = wm * 64 + (lane & 7) + ((lane >> 3) & 1) * 8;
    const uint32_t aKsel = ((lane >> 4) & 1) * 16;
    // B frag: n-row = wn*64 + ng*16 + ((lane>>4)&1)*8 + (lane&7) ; kbyte = kc*32 + bKsel
    const int bRowBase = wn * 64 + ((lane >> 4) & 1) * 8 + (lane & 7);
    const uint32_t bKsel = ((lane >> 3) & 1) * 16;

    load_stage(smb, ah, al, bh, bl, 0, K, tid);
    asm volatile("cp.async.commit_group;" ::: "memory");

    for (int kt = 0; kt < T; kt++) {
        if (kt + 1 < T) {
            load_stage(smb + (uint32_t)((kt + 1) & 1) * STAGE_B, ah, al, bh, bl, kt + 1, K, tid);
            asm volatile("cp.async.commit_group;" ::: "memory");
            asm volatile("cp.async.wait_group 1;" ::: "memory");
        } else {
            asm volatile("cp.async.wait_group 0;" ::: "memory");
        }
        __syncthreads();

        const uint32_t sAh = smb + (uint32_t)(kt & 1) * STAGE_B;
        const uint32_t sAl = sAh + A_TILE_B;
        const uint32_t sBh = sAh + 2u * A_TILE_B;
        const uint32_t sBl = sBh + B_TILE_B;

        #pragma unroll
        for (int kc = 0; kc < 4; kc++) {
            uint32_t fah[4][4], fal[4][4];
            #pragma unroll
            for (int mf = 0; mf < 4; mf++) {
                int row = aRowBase + mf * 16;
                uint32_t kb = (uint32_t)kc * 32 + aKsel;
                uint32_t off = ((uint32_t)row << 7) + (kb ^ (((uint32_t)row & 7u) << 4));
                ldsm_x4(fah[mf], sAh + off);
                ldsm_x4(fal[mf], sAl + off);
            }
            #pragma unroll
            for (int ng = 0; ng < 4; ng++) {
                uint32_t fbh[4], fbl[4];
                int row = bRowBase + ng * 16;
                uint32_t kb = (uint32_t)kc * 32 + bKsel;
                uint32_t off = ((uint32_t)row << 7) + (kb ^ (((uint32_t)row & 7u) << 4));
                ldsm_x4(fbh, sBh + off);
                ldsm_x4(fbl, sBl + off);
                #pragma unroll
                for (int mf = 0; mf < 4; mf++) {
                    #pragma unroll
                    for (int half = 0; half < 2; half++) {
                        float (&d)[4] = acc[mf][ng * 2 + half];
                        mma16816(d, fah[mf], fbh[half * 2], fbh[half * 2 + 1]);
                        mma16816(d, fah[mf], fbl[half * 2], fbl[half * 2 + 1]);
                        mma16816(d, fal[mf], fbh[half * 2], fbh[half * 2 + 1]);
                    }
                }
            }
        }
        __syncthreads();
    }

    // epilogue
    const int r0 = bm * 256 + wm * 64 + (lane >> 2);
    const int c0 = bn * 128 + wn * 64 + (lane & 3) * 2;
    #pragma unroll
    for (int mf = 0; mf < 4; mf++) {
        #pragma unroll
        for (int nf = 0; nf < 8; nf++) {
            float* p0 = C + (size_t)(r0 + mf * 16) * N + c0 + nf * 8;
            float* p1 = C + (size_t)(r0 + mf * 16 + 8) * N + c0 + nf * 8;
            *(float2*)p0 = make_float2(acc[mf][nf][0], acc[mf][nf][1]);
            *(float2*)p1 = make_float2(acc[mf][nf][2], acc[mf][nf][3]);
        }
    }
}

// ---------------------------------------------------------------------------
// BN stats (deterministic two-stage)
// ---------------------------------------------------------------------------
__global__ void __launch_bounds__(256) colstats_partial_kernel(const float* __restrict__ Z, int D)
{
    int col = blockIdx.x * 256 + threadIdx.x;
    size_t base = (size_t)(blockIdx.y * 256) * D + col;
    float s = 0.0f, q = 0.0f;
    #pragma unroll 4
    for (int r = 0; r < 256; r++) {
        float v = Z[base + (size_t)r * D];
        s += v;
        q = fmaf(v, v, q);
    }
    g_PS[blockIdx.y * D + col] = s;
    g_PQ[blockIdx.y * D + col] = q;
}

__global__ void __launch_bounds__(256) bn_finalize_kernel(
    const float* __restrict__ g, const float* __restrict__ be, int D)
{
    int col = blockIdx.x * 256 + threadIdx.x;
    if (col >= D) return;
    float s = 0.0f, q = 0.0f;
    #pragma unroll
    for (int c = 0; c < 64; c++) { s += g_PS[c * D + col]; q += g_PQ[c * D + col]; }
    float invB = 1.0f / (float)BATCH;
    float mean = s * invB;
    float var  = q * invB - mean * mean;
    float sc   = g[col] / sqrtf(var + BN_EPS);
    g_SCALE[col] = sc;
    g_SHIFT[col] = be[col] - mean * sc;
}

// BN+ReLU -> bf16 hi/lo split (feeds next GEMM)
__global__ void __launch_bounds__(256) bn_relu_split_kernel(
    const float* __restrict__ Z, __nv_bfloat16* __restrict__ Ah, __nv_bfloat16* __restrict__ Al,
    int D, int total4)
{
    int i = blockIdx.x * 256 + threadIdx.x;
    if (i >= total4) return;
    int col = (i * 4) % D;
    float4 v = ((const float4*)Z)[i];
    float y0 = fmaxf(0.0f, fmaf(v.x, g_SCALE[col + 0], g_SHIFT[col + 0]));
    float y1 = fmaxf(0.0f, fmaf(v.y, g_SCALE[col + 1], g_SHIFT[col + 1]));
    float y2 = fmaxf(0.0f, fmaf(v.z, g_SCALE[col + 2], g_SHIFT[col + 2]));
    float y3 = fmaxf(0.0f, fmaf(v.w, g_SCALE[col + 3], g_SHIFT[col + 3]));
    __nv_bfloat16 h0, l0, h1, l1, h2, l2, h3, l3;
    split2(y0, h0, l0); split2(y1, h1, l1); split2(y2, h2, l2); split2(y3, h3, l3);
    ((__nv_bfloat162*)Ah)[i * 2 + 0] = __nv_bfloat162(h0, h1);
    ((__nv_bfloat162*)Ah)[i * 2 + 1] = __nv_bfloat162(h2, h3);
    ((__nv_bfloat162*)Al)[i * 2 + 0] = __nv_bfloat162(l0, l1);
    ((__nv_bfloat162*)Al)[i * 2 + 1] = __nv_bfloat162(l2, l3);
}

// BN+ReLU in place (fp32, for layer 2 -> GEMV)
__global__ void __launch_bounds__(256) bn_relu_kernel(float* __restrict__ Z, int D, int total4)
{
    int i = blockIdx.x * 256 + threadIdx.x;
    if (i >= total4) return;
    int col = (i * 4) % D;
    float4 v = ((float4*)Z)[i];
    v.x = fmaxf(0.0f, fmaf(v.x, g_SCALE[col + 0], g_SHIFT[col + 0]));
    v.y = fmaxf(0.0f, fmaf(v.y, g_SCALE[col + 1], g_SHIFT[col + 1]));
    v.z = fmaxf(0.0f, fmaf(v.z, g_SCALE[col + 2], g_SHIFT[col + 2]));
    v.w = fmaxf(0.0f, fmaf(v.w, g_SCALE[col + 3], g_SHIFT[col + 3]));
    ((float4*)Z)[i] = v;
}

// ---------------------------------------------------------------------------
// Output GEMV: out[b] = dot(Z2[b,:1024], Wout) + bout
// ---------------------------------------------------------------------------
__global__ void __launch_bounds__(256) out_gemv_kernel(
    const float* __restrict__ A2, const float* __restrict__ Wout,
    const float* __restrict__ bout, float* __restrict__ out)
{
    __shared__ float w[D3];
    int tid = threadIdx.x;
    ((float4*)w)[tid] = ((const float4*)Wout)[tid];
    __syncthreads();
    int warp = tid >> 5, lane = tid & 31;
    int b = blockIdx.x * 8 + warp;
    const float* a = A2 + (size_t)b * D3;
    float sum = 0.0f;
    #pragma unroll
    for (int it = 0; it < 8; it++) {
        int k = it * 128 + lane * 4;
        float4 av = *(const float4*)(a + k);
        float4 wv = *(const float4*)(w + k);
        sum = fmaf(av.x, wv.x, sum);
        sum = fmaf(av.y, wv.y, sum);
        sum = fmaf(av.z, wv.z, sum);
        sum = fmaf(av.w, wv.w, sum);
    }
    #pragma unroll
    for (int off = 16; off > 0; off >>= 1) sum += __shfl_down_sync(0xFFFFFFFFu, sum, off);
    if (lane == 0) out[b] = sum + bout[0];
}

// ---------------------------------------------------------------------------
// Host launcher. Inputs: 0 xv, 1 W0, 2 b0, 3 g0, 4 be0, 5 W1, 6 b1, 7 g1,
// 8 be1, 9 W2, 10 b2, 11 g2, 12 be2, 13 Wout, 14 bout.
// b0/b1/b2 are absorbed by train-mode BatchNorm and never read.
// ---------------------------------------------------------------------------
extern "C" void kernel_launch(void* const* d_in, const int* in_sizes, int n_in,
                              void* d_out, int out_size)
{
    const float* xv   = (const float*)d_in[0];
    const float* W0   = (const float*)d_in[1];
    const float* g0   = (const float*)d_in[3];
    const float* be0  = (const float*)d_in[4];
    const float* W1   = (const float*)d_in[5];
    const float* g1   = (const float*)d_in[7];
    const float* be1  = (const float*)d_in[8];
    const float* W2   = (const float*)d_in[9];
    const float* g2   = (const float*)d_in[11];
    const float* be2  = (const float*)d_in[12];
    const float* Wout = (const float*)d_in[13];
    const float* bout = (const float*)d_in[14];
    float* out = (float*)d_out;

    cudaFuncSetAttribute(gemm_bf16x3_kernel, cudaFuncAttributeMaxDynamicSharedMemorySize, GEMM_SMEM);

    __nv_bfloat16 *H0h, *H0l, *Ahp, *Alp, *W0h, *W0l, *W1h, *W1l, *W2h, *W2l;
    float *Z;
    cudaGetSymbolAddress((void**)&H0h, g_H0h);
    cudaGetSymbolAddress((void**)&H0l, g_H0l);
    cudaGetSymbolAddress((void**)&Ahp, g_Ah);
    cudaGetSymbolAddress((void**)&Alp, g_Al);
    cudaGetSymbolAddress((void**)&Z,   g_Z);
    cudaGetSymbolAddress((void**)&W0h, g_W0h);
    cudaGetSymbolAddress((void**)&W0l, g_W0l);
    cudaGetSymbolAddress((void**)&W1h, g_W1h);
    cudaGetSymbolAddress((void**)&W1l, g_W1l);
    cudaGetSymbolAddress((void**)&W2h, g_W2h);
    cudaGetSymbolAddress((void**)&W2l, g_W2l);

    // frontend + weight prep
    build_pairs_kernel<<<8, 256>>>();
    build_h0_kernel<<<BATCH, 256>>>(xv);
    split_w_kernel<<<(int)(((size_t)D1 * K0P + 255) / 256), 256>>>(W0, W0h, W0l, D1, K0, K0P);
    split_w_kernel<<<(int)(((size_t)D2 * D1 + 255) / 256), 256>>>(W1, W1h, W1l, D2, D1, D1);
    split_w_kernel<<<(int)(((size_t)D3 * D2 + 255) / 256), 256>>>(W2, W2h, W2l, D3, D2, D2);

    // layer 0: Z = H0 @ W0^T   [16384, 2048], K = 2304
    gemm_bf16x3_kernel<<<dim3(D1 / 128, BATCH / 256), 256, GEMM_SMEM>>>(H0h, H0l, W0h, W0l, Z, BATCH, D1, K0P);
    colstats_partial_kernel<<<dim3(D1 / 256, 64), 256>>>(Z, D1);
    bn_finalize_kernel<<<D1 / 256, 256>>>(g0, be0, D1);
    bn_relu_split_kernel<<<(BATCH * D1 / 4) / 256, 256>>>(Z, Ahp, Alp, D1, BATCH * D1 / 4);

    // layer 1: Z = A @ W1^T    [16384, 2048], K = 2048
    gemm_bf16x3_kernel<<<dim3(D2 / 128, BATCH / 256), 256, GEMM_SMEM>>>(Ahp, Alp, W1h, W1l, Z, BATCH, D2, D1);
    colstats_partial_kernel<<<dim3(D2 / 256, 64), 256>>>(Z, D2);
    bn_finalize_kernel<<<D2 / 256, 256>>>(g1, be1, D2);
    bn_relu_split_kernel<<<(BATCH * D2 / 4) / 256, 256>>>(Z, Ahp, Alp, D2, BATCH * D2 / 4);

    // layer 2: Z = A @ W2^T    [16384, 1024], K = 2048
    gemm_bf16x3_kernel<<<dim3(D3 / 128, BATCH / 256), 256, GEMM_SMEM>>>(Ahp, Alp, W2h, W2l, Z, BATCH, D3, D2);
    colstats_partial_kernel<<<dim3(D3 / 256, 64), 256>>>(Z, D3);
    bn_finalize_kernel<<<D3 / 256, 256>>>(g2, be2, D3);
    bn_relu_kernel<<<(BATCH * D3 / 4) / 256, 256>>>(Z, D3, BATCH * D3 / 4);

    // output head
    out_gemv_kernel<<<BATCH / 8, 256>>>(Z, Wout, bout, out);
}

// round 5
// speedup vs baseline: 7.3565x; 2.3282x over previous
#include <cuda_runtime.h>
#include <cuda_fp16.h>
#include <cstdint>
#include <math.h>

// ---------------------------------------------------------------------------
// Problem constants
// ---------------------------------------------------------------------------
#define BATCH   16384
#define FDIM    256
#define NPAIRS  2016
#define K0      2272
#define K0P     2304          // padded to multiple of 64
#define D1      2048
#define D2      2048
#define D3      1024
#define BN_EPS  1e-5f

// ---------------------------------------------------------------------------
// Scratch (static device arrays; runtime allocation forbidden)
// ---------------------------------------------------------------------------
__device__ __half g_H0[BATCH * (size_t)K0P];          // 75.5 MB
__device__ __half g_A [BATCH * (size_t)D1];           // 67 MB (activations, reused)
__device__ float  g_Z [BATCH * (size_t)D1];           // 134 MB (pre-activation, reused)
__device__ __half g_W0[(size_t)D1 * K0P];
__device__ __half g_W1[(size_t)D2 * D1];
__device__ __half g_W2[(size_t)D3 * D2];
__device__ float g_PS[64 * D1];
__device__ float g_PQ[64 * D1];
__device__ float g_SCALE[D1];
__device__ float g_SHIFT[D1];
__device__ int   g_PI[NPAIRS];
__device__ int   g_PJ[NPAIRS];

// ---------------------------------------------------------------------------
// PTX wrappers (plain sm_80+ features)
// ---------------------------------------------------------------------------
__device__ __forceinline__ uint32_t smem_u32(const void* p) {
    uint32_t a;
    asm("{ .reg .u64 t; cvta.to.shared.u64 t, %1; cvt.u32.u64 %0, t; }" : "=r"(a) : "l"(p));
    return a;
}
__device__ __forceinline__ void cp16(uint32_t saddr, const void* gaddr) {
    asm volatile("cp.async.cg.shared.global [%0], [%1], 16;" :: "r"(saddr), "l"(gaddr));
}
__device__ __forceinline__ void ldsm_x4(uint32_t (&r)[4], uint32_t addr) {
    asm volatile("ldmatrix.sync.aligned.m8n8.x4.shared.b16 {%0,%1,%2,%3}, [%4];"
        : "=r"(r[0]), "=r"(r[1]), "=r"(r[2]), "=r"(r[3]) : "r"(addr));
}
__device__ __forceinline__ void mma16816(float (&d)[4], const uint32_t (&a)[4],
                                         uint32_t b0, uint32_t b1) {
    asm volatile(
        "mma.sync.aligned.m16n8k16.row.col.f32.f16.f16.f32 "
        "{%0,%1,%2,%3}, {%4,%5,%6,%7}, {%8,%9}, {%0,%1,%2,%3};"
        : "+f"(d[0]), "+f"(d[1]), "+f"(d[2]), "+f"(d[3])
        : "r"(a[0]), "r"(a[1]), "r"(a[2]), "r"(a[3]), "r"(b0), "r"(b1));
}

// ---------------------------------------------------------------------------
// Pair table (row-major upper triangle, k=1)
// ---------------------------------------------------------------------------
__global__ void build_pairs_kernel() {
    int p = blockIdx.x * blockDim.x + threadIdx.x;
    if (p >= NPAIRS) return;
    float disc = sqrtf(16129.0f - 8.0f * (float)p);
    int i = (int)((127.0f - disc) * 0.5f);
    while (((127 * (i + 1) - (i + 1) * (i + 1)) >> 1) <= p) i++;
    while (((127 * i - i * i) >> 1) > p) i--;
    int off = (127 * i - i * i) >> 1;
    g_PI[p] = i;
    g_PJ[p] = p - off + i + 1;
}

// ---------------------------------------------------------------------------
// H0 (fp16, zero-padded to K0P) — one block per batch row
// ---------------------------------------------------------------------------
__global__ void __launch_bounds__(256) build_h0_kernel(const float* __restrict__ xv) {
    __shared__ float row[FDIM];
    int b = blockIdx.x;
    int tid = threadIdx.x;
    row[tid] = xv[(size_t)b * FDIM + tid];
    __syncthreads();
    __half* h = g_H0 + (size_t)b * K0P;
    h[tid] = __float2half_rn(row[tid]);
    const float inv255 = 1.0f / 255.0f;
    for (int p = tid; p < NPAIRS; p += 256) {
        h[FDIM + p] = __float2half_rn(row[g_PI[p]] * row[g_PJ[p]] * inv255);
    }
    if (tid < K0P - K0) h[K0 + tid] = __float2half_rn(0.0f);
}

// ---------------------------------------------------------------------------
// Weight convert/pad: W fp32 [N, Kin] -> fp16 [N, Kout] (zero pad tail)
// ---------------------------------------------------------------------------
__global__ void __launch_bounds__(256) convert_w_kernel(
    const float* __restrict__ W, __half* __restrict__ Wh, int N, int Kin, int Kout)
{
    size_t idx = (size_t)blockIdx.x * 256 + threadIdx.x;
    size_t total = (size_t)N * Kout;
    if (idx >= total) return;
    int k = (int)(idx % Kout);
    int n = (int)(idx / Kout);
    float x = (k < Kin) ? W[(size_t)n * Kin + k] : 0.0f;
    Wh[idx] = __float2half_rn(x);
}

// ---------------------------------------------------------------------------
// fp16 mma.sync GEMM with fused column stats:
//   C[M,N] fp32 = A[M,K] @ B[N,K]^T ; also writes per-slab column sum/sumsq
//   into g_PS/g_PQ[bm][bn*128 + col] (deterministic, one CTA per slot).
// CTA 256x128, BK=64, 8 warps (4M x 2N), warp tile 64x64, 4-stage cp.async.
// Stage: A 32KB | B 16KB = 48KB; 4 stages = 192KB smem. SW128 swizzle.
// M mult of 256 (M/256 == 64 slabs), N mult of 128, K mult of 64.
// ---------------------------------------------------------------------------
#define A_TILE_B 32768u
#define B_TILE_B 16384u
#define STAGE_B  (A_TILE_B + B_TILE_B)     // 49152
#define GEMM_SMEM (4u * STAGE_B)           // 196608

__device__ __forceinline__ void load_stage(
    uint32_t sbase, const __half* __restrict__ a, const __half* __restrict__ b,
    int kt, int K, int tid)
{
    const __half* ga = a + (size_t)kt * 64;
    #pragma unroll
    for (int i = 0; i < 8; i++) {
        int idx = tid + i * 256;            // 0..2047
        int row = idx >> 3;                 // 0..255
        int ch  = idx & 7;
        uint32_t off = (uint32_t)(row << 7) + (((uint32_t)ch << 4) ^ (((uint32_t)row & 7u) << 4));
        cp16(sbase + off, ga + (size_t)row * K + (ch << 3));
    }
    const __half* gb = b + (size_t)kt * 64;
    #pragma unroll
    for (int i = 0; i < 4; i++) {
        int idx = tid + i * 256;            // 0..1023
        int row = idx >> 3;                 // 0..127
        int ch  = idx & 7;
        uint32_t off = (uint32_t)(row << 7) + (((uint32_t)ch << 4) ^ (((uint32_t)row & 7u) << 4));
        cp16(sbase + A_TILE_B + off, gb + (size_t)row * K + (ch << 3));
    }
}

__global__ void __launch_bounds__(256, 1) gemm_f16_kernel(
    const __half* __restrict__ A, const __half* __restrict__ B,
    float* __restrict__ C, int M, int N, int K)
{
    extern __shared__ char smraw[];
    const uint32_t smb = smem_u32(smraw);
    const int tid  = threadIdx.x;
    const int wid  = tid >> 5;
    const int lane = tid & 31;
    const int wm = wid & 3;            // 0..3  (M dir, 64 rows each)
    const int wn = wid >> 2;           // 0..1  (N dir, 64 cols each)
    const int bn = blockIdx.x, bm = blockIdx.y;
    const int T = K >> 6;

    const __half* a = A + (size_t)bm * 256 * K;
    const __half* b = B + (size_t)bn * 128 * K;

    float acc[4][8][4];
    #pragma unroll
    for (int x = 0; x < 4; x++)
        #pragma unroll
        for (int y = 0; y < 8; y++)
            #pragma unroll
            for (int z = 0; z < 4; z++) acc[x][y][z] = 0.0f;

    const int aRowBase = wm * 64 + (lane & 7) + ((lane >> 3) & 1) * 8;
    const uint32_t aKsel = ((lane >> 4) & 1) * 16;
    const int bRowBase = wn * 64 + ((lane >> 4) & 1) * 8 + (lane & 7);
    const uint32_t bKsel = ((lane >> 3) & 1) * 16;

    // prologue: stages 0,1,2
    #pragma unroll
    for (int s = 0; s < 3; s++) {
        load_stage(smb + (uint32_t)s * STAGE_B, a, b, s, K, tid);
        asm volatile("cp.async.commit_group;" ::: "memory");
    }

    for (int kt = 0; kt < T; kt++) {
        if (kt + 2 < T)      asm volatile("cp.async.wait_group 2;" ::: "memory");
        else if (kt + 1 < T) asm volatile("cp.async.wait_group 1;" ::: "memory");
        else                 asm volatile("cp.async.wait_group 0;" ::: "memory");
        __syncthreads();

        if (kt + 3 < T) {
            load_stage(smb + (uint32_t)((kt + 3) & 3) * STAGE_B, a, b, kt + 3, K, tid);
            asm volatile("cp.async.commit_group;" ::: "memory");
        }

        const uint32_t sA = smb + (uint32_t)(kt & 3) * STAGE_B;
        const uint32_t sB = sA + A_TILE_B;

        #pragma unroll
        for (int kc = 0; kc < 4; kc++) {
            uint32_t fa[4][4];
            #pragma unroll
            for (int mf = 0; mf < 4; mf++) {
                int row = aRowBase + mf * 16;
                uint32_t kb = (uint32_t)kc * 32 + aKsel;
                uint32_t off = ((uint32_t)row << 7) + (kb ^ (((uint32_t)row & 7u) << 4));
                ldsm_x4(fa[mf], sA + off);
            }
            #pragma unroll
            for (int ng = 0; ng < 4; ng++) {
                uint32_t fb[4];
                int row = bRowBase + ng * 16;
                uint32_t kb = (uint32_t)kc * 32 + bKsel;
                uint32_t off = ((uint32_t)row << 7) + (kb ^ (((uint32_t)row & 7u) << 4));
                ldsm_x4(fb, sB + off);
                #pragma unroll
                for (int mf = 0; mf < 4; mf++) {
                    mma16816(acc[mf][ng * 2 + 0], fa[mf], fb[0], fb[1]);
                    mma16816(acc[mf][ng * 2 + 1], fa[mf], fb[2], fb[3]);
                }
            }
        }
    }
    __syncthreads();   // all smem reads done; stage memory is now reusable

    // ---- store C ----
    const int r0 = bm * 256 + wm * 64 + (lane >> 2);
    const int c0 = bn * 128 + wn * 64 + (lane & 3) * 2;
    #pragma unroll
    for (int mf = 0; mf < 4; mf++) {
        #pragma unroll
        for (int nf = 0; nf < 8; nf++) {
            float* p0 = C + (size_t)(r0 + mf * 16) * N + c0 + nf * 8;
            float* p1 = C + (size_t)(r0 + mf * 16 + 8) * N + c0 + nf * 8;
            *(float2*)p0 = make_float2(acc[mf][nf][0], acc[mf][nf][1]);
            *(float2*)p1 = make_float2(acc[mf][nf][2], acc[mf][nf][3]);
        }
    }

    // ---- fused column stats: partial sum & sumsq over this CTA's 256 rows ----
    // lane-local partials over its 8 row-samples per column
    float se[8], so[8], qe[8], qo[8];
    #pragma unroll
    for (int nf = 0; nf < 8; nf++) {
        float s0 = 0.f, s1 = 0.f, q0 = 0.f, q1 = 0.f;
        #pragma unroll
        for (int mf = 0; mf < 4; mf++) {
            float a0 = acc[mf][nf][0], a1 = acc[mf][nf][1];
            float a2 = acc[mf][nf][2], a3 = acc[mf][nf][3];
            s0 += a0 + a2;  s1 += a1 + a3;
            q0 = fmaf(a0, a0, fmaf(a2, a2, q0));
            q1 = fmaf(a1, a1, fmaf(a3, a3, q1));
        }
        se[nf] = s0; so[nf] = s1; qe[nf] = q0; qo[nf] = q1;
    }
    // reduce over the 8 lanes that share (lane&3): xor 4, 8, 16
    #pragma unroll
    for (int off = 4; off <= 16; off <<= 1) {
        #pragma unroll
        for (int nf = 0; nf < 8; nf++) {
            se[nf] += __shfl_xor_sync(0xffffffffu, se[nf], off);
            so[nf] += __shfl_xor_sync(0xffffffffu, so[nf], off);
            qe[nf] += __shfl_xor_sync(0xffffffffu, qe[nf], off);
            qo[nf] += __shfl_xor_sync(0xffffffffu, qo[nf], off);
        }
    }
    float* ss = (float*)smraw;           // [4][128]
    float* sq = ss + 512;                // [4][128]
    if ((lane >> 2) == 0) {
        #pragma unroll
        for (int nf = 0; nf < 8; nf++) {
            int col = wn * 64 + nf * 8 + (lane & 3) * 2;
            ss[wm * 128 + col]     = se[nf];
            ss[wm * 128 + col + 1] = so[nf];
            sq[wm * 128 + col]     = qe[nf];
            sq[wm * 128 + col + 1] = qo[nf];
        }
    }
    __syncthreads();
    if (tid < 128) {
        float t = ss[tid] + ss[128 + tid] + ss[256 + tid] + ss[384 + tid];
        g_PS[(size_t)bm * N + bn * 128 + tid] = t;
    } else if (tid < 256) {
        int c = tid - 128;
        float t = sq[c] + sq[128 + c] + sq[256 + c] + sq[384 + c];
        g_PQ[(size_t)bm * N + bn * 128 + c] = t;
    }
}

// ---------------------------------------------------------------------------
// BN finalize: reduce 64 partials -> per-column scale/shift
// ---------------------------------------------------------------------------
__global__ void __launch_bounds__(256) bn_finalize_kernel(
    const float* __restrict__ g, const float* __restrict__ be, int D)
{
    int col = blockIdx.x * 256 + threadIdx.x;
    if (col >= D) return;
    float s = 0.0f, q = 0.0f;
    #pragma unroll
    for (int c = 0; c < 64; c++) { s += g_PS[c * D + col]; q += g_PQ[c * D + col]; }
    float invB = 1.0f / (float)BATCH;
    float mean = s * invB;
    float var  = q * invB - mean * mean;
    float sc   = g[col] / sqrtf(var + BN_EPS);
    g_SCALE[col] = sc;
    g_SHIFT[col] = be[col] - mean * sc;
}

// BN+ReLU -> fp16 (feeds next GEMM)
__global__ void __launch_bounds__(256) bn_relu_half_kernel(
    const float* __restrict__ Z, __half* __restrict__ Ao, int D, int total4)
{
    int i = blockIdx.x * 256 + threadIdx.x;
    if (i >= total4) return;
    int col = (i * 4) % D;
    float4 v = ((const float4*)Z)[i];
    float y0 = fmaxf(0.0f, fmaf(v.x, g_SCALE[col + 0], g_SHIFT[col + 0]));
    float y1 = fmaxf(0.0f, fmaf(v.y, g_SCALE[col + 1], g_SHIFT[col + 1]));
    float y2 = fmaxf(0.0f, fmaf(v.z, g_SCALE[col + 2], g_SHIFT[col + 2]));
    float y3 = fmaxf(0.0f, fmaf(v.w, g_SCALE[col + 3], g_SHIFT[col + 3]));
    ((__half2*)Ao)[i * 2 + 0] = __floats2half2_rn(y0, y1);
    ((__half2*)Ao)[i * 2 + 1] = __floats2half2_rn(y2, y3);
}

// BN+ReLU in place (fp32, for layer 2 -> GEMV)
__global__ void __launch_bounds__(256) bn_relu_kernel(float* __restrict__ Z, int D, int total4)
{
    int i = blockIdx.x * 256 + threadIdx.x;
    if (i >= total4) return;
    int col = (i * 4) % D;
    float4 v = ((float4*)Z)[i];
    v.x = fmaxf(0.0f, fmaf(v.x, g_SCALE[col + 0], g_SHIFT[col + 0]));
    v.y = fmaxf(0.0f, fmaf(v.y, g_SCALE[col + 1], g_SHIFT[col + 1]));
    v.z = fmaxf(0.0f, fmaf(v.z, g_SCALE[col + 2], g_SHIFT[col + 2]));
    v.w = fmaxf(0.0f, fmaf(v.w, g_SCALE[col + 3], g_SHIFT[col + 3]));
    ((float4*)Z)[i] = v;
}

// ---------------------------------------------------------------------------
// Output GEMV: out[b] = dot(Z2[b,:1024], Wout) + bout
// ---------------------------------------------------------------------------
__global__ void __launch_bounds__(256) out_gemv_kernel(
    const float* __restrict__ A2, const float* __restrict__ Wout,
    const float* __restrict__ bout, float* __restrict__ out)
{
    __shared__ float w[D3];
    int tid = threadIdx.x;
    ((float4*)w)[tid] = ((const float4*)Wout)[tid];
    __syncthreads();
    int warp = tid >> 5, lane = tid & 31;
    int b = blockIdx.x * 8 + warp;
    const float* a = A2 + (size_t)b * D3;
    float sum = 0.0f;
    #pragma unroll
    for (int it = 0; it < 8; it++) {
        int k = it * 128 + lane * 4;
        float4 av = *(const float4*)(a + k);
        float4 wv = *(const float4*)(w + k);
        sum = fmaf(av.x, wv.x, sum);
        sum = fmaf(av.y, wv.y, sum);
        sum = fmaf(av.z, wv.z, sum);
        sum = fmaf(av.w, wv.w, sum);
    }
    #pragma unroll
    for (int off = 16; off > 0; off >>= 1) sum += __shfl_down_sync(0xFFFFFFFFu, sum, off);
    if (lane == 0) out[b] = sum + bout[0];
}

// ---------------------------------------------------------------------------
// Host launcher. Inputs: 0 xv, 1 W0, 2 b0, 3 g0, 4 be0, 5 W1, 6 b1, 7 g1,
// 8 be1, 9 W2, 10 b2, 11 g2, 12 be2, 13 Wout, 14 bout.
// b0/b1/b2 are absorbed by train-mode BatchNorm and never read.
// ---------------------------------------------------------------------------
extern "C" void kernel_launch(void* const* d_in, const int* in_sizes, int n_in,
                              void* d_out, int out_size)
{
    const float* xv   = (const float*)d_in[0];
    const float* W0   = (const float*)d_in[1];
    const float* g0   = (const float*)d_in[3];
    const float* be0  = (const float*)d_in[4];
    const float* W1   = (const float*)d_in[5];
    const float* g1   = (const float*)d_in[7];
    const float* be1  = (const float*)d_in[8];
    const float* W2   = (const float*)d_in[9];
    const float* g2   = (const float*)d_in[11];
    const float* be2  = (const float*)d_in[12];
    const float* Wout = (const float*)d_in[13];
    const float* bout = (const float*)d_in[14];
    float* out = (float*)d_out;

    cudaFuncSetAttribute(gemm_f16_kernel, cudaFuncAttributeMaxDynamicSharedMemorySize, GEMM_SMEM);

    __half *H0, *Ap, *W0h, *W1h, *W2h;
    float *Z;
    cudaGetSymbolAddress((void**)&H0,  g_H0);
    cudaGetSymbolAddress((void**)&Ap,  g_A);
    cudaGetSymbolAddress((void**)&Z,   g_Z);
    cudaGetSymbolAddress((void**)&W0h, g_W0);
    cudaGetSymbolAddress((void**)&W1h, g_W1);
    cudaGetSymbolAddress((void**)&W2h, g_W2);

    // frontend + weight prep
    build_pairs_kernel<<<8, 256>>>();
    build_h0_kernel<<<BATCH, 256>>>(xv);
    convert_w_kernel<<<(int)(((size_t)D1 * K0P + 255) / 256), 256>>>(W0, W0h, D1, K0, K0P);
    convert_w_kernel<<<(int)(((size_t)D2 * D1 + 255) / 256), 256>>>(W1, W1h, D2, D1, D1);
    convert_w_kernel<<<(int)(((size_t)D3 * D2 + 255) / 256), 256>>>(W2, W2h, D3, D2, D2);

    // layer 0: Z = H0 @ W0^T   [16384, 2048], K = 2304   (stats fused)
    gemm_f16_kernel<<<dim3(D1 / 128, BATCH / 256), 256, GEMM_SMEM>>>(H0, W0h, Z, BATCH, D1, K0P);
    bn_finalize_kernel<<<D1 / 256, 256>>>(g0, be0, D1);
    bn_relu_half_kernel<<<(BATCH * D1 / 4) / 256, 256>>>(Z, Ap, D1, BATCH * D1 / 4);

    // layer 1: Z = A @ W1^T    [16384, 2048], K = 2048
    gemm_f16_kernel<<<dim3(D2 / 128, BATCH / 256), 256, GEMM_SMEM>>>(Ap, W1h, Z, BATCH, D2, D1);
    bn_finalize_kernel<<<D2 / 256, 256>>>(g1, be1, D2);
    bn_relu_half_kernel<<<(BATCH * D2 / 4) / 256, 256>>>(Z, Ap, D2, BATCH * D2 / 4);

    // layer 2: Z = A @ W2^T    [16384, 1024], K = 2048
    gemm_f16_kernel<<<dim3(D3 / 128, BATCH / 256), 256, GEMM_SMEM>>>(Ap, W2h, Z, BATCH, D3, D2);
    bn_finalize_kernel<<<D3 / 256, 256>>>(g2, be2, D3);
    bn_relu_kernel<<<(BATCH * D3 / 4) / 256, 256>>>(Z, D3, BATCH * D3 / 4);

    // output head
    out_gemv_kernel<<<BATCH / 8, 256>>>(Z, Wout, bout, out);
}

// round 6
// speedup vs baseline: 8.2488x; 1.1213x over previous
#include <cuda_runtime.h>
#include <cuda_fp16.h>
#include <cstdint>
#include <math.h>

// ---------------------------------------------------------------------------
// Problem constants
// ---------------------------------------------------------------------------
#define BATCH   16384
#define FDIM    256
#define NPAIRS  2016
#define K0      2272
#define K0P     2304          // padded to multiple of 64
#define D1      2048
#define D2      2048
#define D3      1024
#define BN_EPS  1e-5f
#define NSLAB   128           // BATCH / 128 M-slabs (one stats partial each)

// ---------------------------------------------------------------------------
// Scratch (static device arrays; runtime allocation forbidden)
// ---------------------------------------------------------------------------
__device__ __half g_H0[BATCH * (size_t)K0P];          // 75.5 MB
__device__ __half g_A [BATCH * (size_t)D1];           // 67 MB (activations, reused)
__device__ float  g_Z [BATCH * (size_t)D1];           // 134 MB (pre-activation, reused)
__device__ __half g_W0[(size_t)D1 * K0P];
__device__ __half g_W1[(size_t)D2 * D1];
__device__ __half g_W2[(size_t)D3 * D2];
__device__ float g_PS[NSLAB * D1];
__device__ float g_PQ[NSLAB * D1];
__device__ float g_SCALE[D1];
__device__ float g_SHIFT[D1];
__device__ int   g_PI[NPAIRS];
__device__ int   g_PJ[NPAIRS];

// ---------------------------------------------------------------------------
// PTX wrappers (plain sm_80+ features)
// ---------------------------------------------------------------------------
__device__ __forceinline__ uint32_t smem_u32(const void* p) {
    uint32_t a;
    asm("{ .reg .u64 t; cvta.to.shared.u64 t, %1; cvt.u32.u64 %0, t; }" : "=r"(a) : "l"(p));
    return a;
}
__device__ __forceinline__ void cp16(uint32_t saddr, const void* gaddr) {
    asm volatile("cp.async.cg.shared.global [%0], [%1], 16;" :: "r"(saddr), "l"(gaddr));
}
__device__ __forceinline__ void ldsm_x4(uint32_t (&r)[4], uint32_t addr) {
    asm volatile("ldmatrix.sync.aligned.m8n8.x4.shared.b16 {%0,%1,%2,%3}, [%4];"
        : "=r"(r[0]), "=r"(r[1]), "=r"(r[2]), "=r"(r[3]) : "r"(addr));
}
__device__ __forceinline__ void mma16816(float (&d)[4], const uint32_t (&a)[4],
                                         uint32_t b0, uint32_t b1) {
    asm volatile(
        "mma.sync.aligned.m16n8k16.row.col.f32.f16.f16.f32 "
        "{%0,%1,%2,%3}, {%4,%5,%6,%7}, {%8,%9}, {%0,%1,%2,%3};"
        : "+f"(d[0]), "+f"(d[1]), "+f"(d[2]), "+f"(d[3])
        : "r"(a[0]), "r"(a[1]), "r"(a[2]), "r"(a[3]), "r"(b0), "r"(b1));
}

// ---------------------------------------------------------------------------
// Pair table (row-major upper triangle, k=1)
// ---------------------------------------------------------------------------
__global__ void build_pairs_kernel() {
    int p = blockIdx.x * blockDim.x + threadIdx.x;
    if (p >= NPAIRS) return;
    float disc = sqrtf(16129.0f - 8.0f * (float)p);
    int i = (int)((127.0f - disc) * 0.5f);
    while (((127 * (i + 1) - (i + 1) * (i + 1)) >> 1) <= p) i++;
    while (((127 * i - i * i) >> 1) > p) i--;
    int off = (127 * i - i * i) >> 1;
    g_PI[p] = i;
    g_PJ[p] = p - off + i + 1;
}

// ---------------------------------------------------------------------------
// H0 (fp16, zero-padded to K0P) — one block per batch row
// ---------------------------------------------------------------------------
__global__ void __launch_bounds__(256) build_h0_kernel(const float* __restrict__ xv) {
    __shared__ float row[FDIM];
    int b = blockIdx.x;
    int tid = threadIdx.x;
    row[tid] = xv[(size_t)b * FDIM + tid];
    __syncthreads();
    __half* h = g_H0 + (size_t)b * K0P;
    h[tid] = __float2half_rn(row[tid]);
    const float inv255 = 1.0f / 255.0f;
    for (int p = tid; p < NPAIRS; p += 256) {
        h[FDIM + p] = __float2half_rn(row[g_PI[p]] * row[g_PJ[p]] * inv255);
    }
    if (tid < K0P - K0) h[K0 + tid] = __float2half_rn(0.0f);
}

// ---------------------------------------------------------------------------
// Weight convert/pad: W fp32 [N, Kin] -> fp16 [N, Kout] (zero pad tail)
// ---------------------------------------------------------------------------
__global__ void __launch_bounds__(256) convert_w_kernel(
    const float* __restrict__ W, __half* __restrict__ Wh, int N, int Kin, int Kout)
{
    size_t idx = (size_t)blockIdx.x * 256 + threadIdx.x;
    size_t total = (size_t)N * Kout;
    if (idx >= total) return;
    int k = (int)(idx % Kout);
    int n = (int)(idx / Kout);
    float x = (k < Kin) ? W[(size_t)n * Kin + k] : 0.0f;
    Wh[idx] = __float2half_rn(x);
}

// ---------------------------------------------------------------------------
// fp16 mma.sync GEMM with fused column stats:
//   C[M,N] fp32 = A[M,K] @ B[N,K]^T ; per-128-row-slab column sum/sumsq
//   into g_PS/g_PQ[bm][bn*128 + col] (deterministic, one CTA per slot).
// CTA 128x128, BK=64, 4 warps (2M x 2N), warp tile 64x64, 3-stage cp.async.
// Stage: A 16KB | B 16KB = 32KB; 3 stages = 96KB smem -> 2 CTAs/SM.
// M mult of 128, N mult of 128, K mult of 64.
// ---------------------------------------------------------------------------
#define A_TILE_B 16384u
#define B_TILE_B 16384u
#define STAGE_B  (A_TILE_B + B_TILE_B)     // 32768
#define GEMM_SMEM (3u * STAGE_B)           // 98304

__device__ __forceinline__ void load_stage(
    uint32_t sbase, const __half* __restrict__ a, const __half* __restrict__ b,
    int kt, int K, int tid)
{
    const __half* ga = a + (size_t)kt * 64;
    #pragma unroll
    for (int i = 0; i < 8; i++) {
        int idx = tid + i * 128;            // 0..1023
        int row = idx >> 3;                 // 0..127
        int ch  = idx & 7;
        uint32_t off = (uint32_t)(row << 7) + (((uint32_t)ch << 4) ^ (((uint32_t)row & 7u) << 4));
        cp16(sbase + off, ga + (size_t)row * K + (ch << 3));
    }
    const __half* gb = b + (size_t)kt * 64;
    #pragma unroll
    for (int i = 0; i < 8; i++) {
        int idx = tid + i * 128;
        int row = idx >> 3;
        int ch  = idx & 7;
        uint32_t off = (uint32_t)(row << 7) + (((uint32_t)ch << 4) ^ (((uint32_t)row & 7u) << 4));
        cp16(sbase + A_TILE_B + off, gb + (size_t)row * K + (ch << 3));
    }
}

__global__ void __launch_bounds__(128, 2) gemm_f16_kernel(
    const __half* __restrict__ A, const __half* __restrict__ B,
    float* __restrict__ C, int M, int N, int K)
{
    extern __shared__ char smraw[];
    const uint32_t smb = smem_u32(smraw);
    const int tid  = threadIdx.x;
    const int wid  = tid >> 5;
    const int lane = tid & 31;
    const int wm = wid & 1;            // 0..1  (M dir, 64 rows each)
    const int wn = wid >> 1;           // 0..1  (N dir, 64 cols each)
    const int bn = blockIdx.x, bm = blockIdx.y;
    const int T = K >> 6;

    const __half* a = A + (size_t)bm * 128 * K;
    const __half* b = B + (size_t)bn * 128 * K;

    float acc[4][8][4];
    #pragma unroll
    for (int x = 0; x < 4; x++)
        #pragma unroll
        for (int y = 0; y < 8; y++)
            #pragma unroll
            for (int z = 0; z < 4; z++) acc[x][y][z] = 0.0f;

    const int aRowBase = wm * 64 + (lane & 7) + ((lane >> 3) & 1) * 8;
    const uint32_t aKsel = ((lane >> 4) & 1) * 16;
    const int bRowBase = wn * 64 + ((lane >> 4) & 1) * 8 + (lane & 7);
    const uint32_t bKsel = ((lane >> 3) & 1) * 16;

    // prologue: stages 0,1
    #pragma unroll
    for (int s = 0; s < 2; s++) {
        load_stage(smb + (uint32_t)s * STAGE_B, a, b, s, K, tid);
        asm volatile("cp.async.commit_group;" ::: "memory");
    }

    int buf = 0;
    for (int kt = 0; kt < T; kt++) {
        if (kt + 1 < T) asm volatile("cp.async.wait_group 1;" ::: "memory");
        else            asm volatile("cp.async.wait_group 0;" ::: "memory");
        __syncthreads();

        if (kt + 2 < T) {
            int nb = kt + 2 - 3 * ((kt + 2) / 3);
            load_stage(smb + (uint32_t)nb * STAGE_B, a, b, kt + 2, K, tid);
            asm volatile("cp.async.commit_group;" ::: "memory");
        }

        const uint32_t sA = smb + (uint32_t)buf * STAGE_B;
        const uint32_t sB = sA + A_TILE_B;

        #pragma unroll
        for (int kc = 0; kc < 4; kc++) {
            uint32_t fa[4][4];
            #pragma unroll
            for (int mf = 0; mf < 4; mf++) {
                int row = aRowBase + mf * 16;
                uint32_t kb = (uint32_t)kc * 32 + aKsel;
                uint32_t off = ((uint32_t)row << 7) + (kb ^ (((uint32_t)row & 7u) << 4));
                ldsm_x4(fa[mf], sA + off);
            }
            #pragma unroll
            for (int ng = 0; ng < 4; ng++) {
                uint32_t fb[4];
                int row = bRowBase + ng * 16;
                uint32_t kb = (uint32_t)kc * 32 + bKsel;
                uint32_t off = ((uint32_t)row << 7) + (kb ^ (((uint32_t)row & 7u) << 4));
                ldsm_x4(fb, sB + off);
                #pragma unroll
                for (int mf = 0; mf < 4; mf++) {
                    mma16816(acc[mf][ng * 2 + 0], fa[mf], fb[0], fb[1]);
                    mma16816(acc[mf][ng * 2 + 1], fa[mf], fb[2], fb[3]);
                }
            }
        }
        buf++;
        if (buf == 3) buf = 0;
        __syncthreads();
    }

    // ---- store C ----
    const int r0 = bm * 128 + wm * 64 + (lane >> 2);
    const int c0 = bn * 128 + wn * 64 + (lane & 3) * 2;
    #pragma unroll
    for (int mf = 0; mf < 4; mf++) {
        #pragma unroll
        for (int nf = 0; nf < 8; nf++) {
            float* p0 = C + (size_t)(r0 + mf * 16) * N + c0 + nf * 8;
            float* p1 = C + (size_t)(r0 + mf * 16 + 8) * N + c0 + nf * 8;
            *(float2*)p0 = make_float2(acc[mf][nf][0], acc[mf][nf][1]);
            *(float2*)p1 = make_float2(acc[mf][nf][2], acc[mf][nf][3]);
        }
    }

    // ---- fused column stats over this CTA's 128 rows ----
    float se[8], so[8], qe[8], qo[8];
    #pragma unroll
    for (int nf = 0; nf < 8; nf++) {
        float s0 = 0.f, s1 = 0.f, q0 = 0.f, q1 = 0.f;
        #pragma unroll
        for (int mf = 0; mf < 4; mf++) {
            float a0 = acc[mf][nf][0], a1 = acc[mf][nf][1];
            float a2 = acc[mf][nf][2], a3 = acc[mf][nf][3];
            s0 += a0 + a2;  s1 += a1 + a3;
            q0 = fmaf(a0, a0, fmaf(a2, a2, q0));
            q1 = fmaf(a1, a1, fmaf(a3, a3, q1));
        }
        se[nf] = s0; so[nf] = s1; qe[nf] = q0; qo[nf] = q1;
    }
    #pragma unroll
    for (int off = 4; off <= 16; off <<= 1) {
        #pragma unroll
        for (int nf = 0; nf < 8; nf++) {
            se[nf] += __shfl_xor_sync(0xffffffffu, se[nf], off);
            so[nf] += __shfl_xor_sync(0xffffffffu, so[nf], off);
            qe[nf] += __shfl_xor_sync(0xffffffffu, qe[nf], off);
            qo[nf] += __shfl_xor_sync(0xffffffffu, qo[nf], off);
        }
    }
    float* ss = (float*)smraw;           // [2][128]
    float* sq = ss + 256;                // [2][128]
    if ((lane >> 2) == 0) {
        #pragma unroll
        for (int nf = 0; nf < 8; nf++) {
            int col = wn * 64 + nf * 8 + (lane & 3) * 2;
            ss[wm * 128 + col]     = se[nf];
            ss[wm * 128 + col + 1] = so[nf];
            sq[wm * 128 + col]     = qe[nf];
            sq[wm * 128 + col + 1] = qo[nf];
        }
    }
    __syncthreads();
    if (tid < 128) {
        g_PS[(size_t)bm * N + bn * 128 + tid] = ss[tid] + ss[128 + tid];
        g_PQ[(size_t)bm * N + bn * 128 + tid] = sq[tid] + sq[128 + tid];
    }
}

// ---------------------------------------------------------------------------
// BN finalize: reduce NSLAB partials -> per-column scale/shift
// ---------------------------------------------------------------------------
__global__ void __launch_bounds__(256) bn_finalize_kernel(
    const float* __restrict__ g, const float* __restrict__ be, int D)
{
    int col = blockIdx.x * 256 + threadIdx.x;
    if (col >= D) return;
    float s = 0.0f, q = 0.0f;
    #pragma unroll 8
    for (int c = 0; c < NSLAB; c++) { s += g_PS[c * D + col]; q += g_PQ[c * D + col]; }
    float invB = 1.0f / (float)BATCH;
    float mean = s * invB;
    float var  = q * invB - mean * mean;
    float sc   = g[col] / sqrtf(var + BN_EPS);
    g_SCALE[col] = sc;
    g_SHIFT[col] = be[col] - mean * sc;
}

// BN+ReLU -> fp16 (feeds next GEMM)
__global__ void __launch_bounds__(256) bn_relu_half_kernel(
    const float* __restrict__ Z, __half* __restrict__ Ao, int D, int total4)
{
    int i = blockIdx.x * 256 + threadIdx.x;
    if (i >= total4) return;
    int col = (i * 4) % D;
    float4 v = ((const float4*)Z)[i];
    float y0 = fmaxf(0.0f, fmaf(v.x, g_SCALE[col + 0], g_SHIFT[col + 0]));
    float y1 = fmaxf(0.0f, fmaf(v.y, g_SCALE[col + 1], g_SHIFT[col + 1]));
    float y2 = fmaxf(0.0f, fmaf(v.z, g_SCALE[col + 2], g_SHIFT[col + 2]));
    float y3 = fmaxf(0.0f, fmaf(v.w, g_SCALE[col + 3], g_SHIFT[col + 3]));
    ((__half2*)Ao)[i * 2 + 0] = __floats2half2_rn(y0, y1);
    ((__half2*)Ao)[i * 2 + 1] = __floats2half2_rn(y2, y3);
}

// BN+ReLU in place (fp32, for layer 2 -> GEMV)
__global__ void __launch_bounds__(256) bn_relu_kernel(float* __restrict__ Z, int D, int total4)
{
    int i = blockIdx.x * 256 + threadIdx.x;
    if (i >= total4) return;
    int col = (i * 4) % D;
    float4 v = ((float4*)Z)[i];
    v.x = fmaxf(0.0f, fmaf(v.x, g_SCALE[col + 0], g_SHIFT[col + 0]));
    v.y = fmaxf(0.0f, fmaf(v.y, g_SCALE[col + 1], g_SHIFT[col + 1]));
    v.z = fmaxf(0.0f, fmaf(v.z, g_SCALE[col + 2], g_SHIFT[col + 2]));
    v.w = fmaxf(0.0f, fmaf(v.w, g_SCALE[col + 3], g_SHIFT[col + 3]));
    ((float4*)Z)[i] = v;
}

// ---------------------------------------------------------------------------
// Output GEMV: out[b] = dot(Z2[b,:1024], Wout) + bout
// ---------------------------------------------------------------------------
__global__ void __launch_bounds__(256) out_gemv_kernel(
    const float* __restrict__ A2, const float* __restrict__ Wout,
    const float* __restrict__ bout, float* __restrict__ out)
{
    __shared__ float w[D3];
    int tid = threadIdx.x;
    ((float4*)w)[tid] = ((const float4*)Wout)[tid];
    __syncthreads();
    int warp = tid >> 5, lane = tid & 31;
    int b = blockIdx.x * 8 + warp;
    const float* a = A2 + (size_t)b * D3;
    float sum = 0.0f;
    #pragma unroll
    for (int it = 0; it < 8; it++) {
        int k = it * 128 + lane * 4;
        float4 av = *(const float4*)(a + k);
        float4 wv = *(const float4*)(w + k);
        sum = fmaf(av.x, wv.x, sum);
        sum = fmaf(av.y, wv.y, sum);
        sum = fmaf(av.z, wv.z, sum);
        sum = fmaf(av.w, wv.w, sum);
    }
    #pragma unroll
    for (int off = 16; off > 0; off >>= 1) sum += __shfl_down_sync(0xFFFFFFFFu, sum, off);
    if (lane == 0) out[b] = sum + bout[0];
}

// ---------------------------------------------------------------------------
// Host launcher. Inputs: 0 xv, 1 W0, 2 b0, 3 g0, 4 be0, 5 W1, 6 b1, 7 g1,
// 8 be1, 9 W2, 10 b2, 11 g2, 12 be2, 13 Wout, 14 bout.
// b0/b1/b2 are absorbed by train-mode BatchNorm and never read.
// ---------------------------------------------------------------------------
extern "C" void kernel_launch(void* const* d_in, const int* in_sizes, int n_in,
                              void* d_out, int out_size)
{
    const float* xv   = (const float*)d_in[0];
    const float* W0   = (const float*)d_in[1];
    const float* g0   = (const float*)d_in[3];
    const float* be0  = (const float*)d_in[4];
    const float* W1   = (const float*)d_in[5];
    const float* g1   = (const float*)d_in[7];
    const float* be1  = (const float*)d_in[8];
    const float* W2   = (const float*)d_in[9];
    const float* g2   = (const float*)d_in[11];
    const float* be2  = (const float*)d_in[12];
    const float* Wout = (const float*)d_in[13];
    const float* bout = (const float*)d_in[14];
    float* out = (float*)d_out;

    cudaFuncSetAttribute(gemm_f16_kernel, cudaFuncAttributeMaxDynamicSharedMemorySize, GEMM_SMEM);

    __half *H0, *Ap, *W0h, *W1h, *W2h;
    float *Z;
    cudaGetSymbolAddress((void**)&H0,  g_H0);
    cudaGetSymbolAddress((void**)&Ap,  g_A);
    cudaGetSymbolAddress((void**)&Z,   g_Z);
    cudaGetSymbolAddress((void**)&W0h, g_W0);
    cudaGetSymbolAddress((void**)&W1h, g_W1);
    cudaGetSymbolAddress((void**)&W2h, g_W2);

    // frontend + weight prep
    build_pairs_kernel<<<8, 256>>>();
    build_h0_kernel<<<BATCH, 256>>>(xv);
    convert_w_kernel<<<(int)(((size_t)D1 * K0P + 255) / 256), 256>>>(W0, W0h, D1, K0, K0P);
    convert_w_kernel<<<(int)(((size_t)D2 * D1 + 255) / 256), 256>>>(W1, W1h, D2, D1, D1);
    convert_w_kernel<<<(int)(((size_t)D3 * D2 + 255) / 256), 256>>>(W2, W2h, D3, D2, D2);

    // layer 0: Z = H0 @ W0^T   [16384, 2048], K = 2304   (stats fused)
    gemm_f16_kernel<<<dim3(D1 / 128, BATCH / 128), 128, GEMM_SMEM>>>(H0, W0h, Z, BATCH, D1, K0P);
    bn_finalize_kernel<<<D1 / 256, 256>>>(g0, be0, D1);
    bn_relu_half_kernel<<<(BATCH * D1 / 4) / 256, 256>>>(Z, Ap, D1, BATCH * D1 / 4);

    // layer 1: Z = A @ W1^T    [16384, 2048], K = 2048
    gemm_f16_kernel<<<dim3(D2 / 128, BATCH / 128), 128, GEMM_SMEM>>>(Ap, W1h, Z, BATCH, D2, D1);
    bn_finalize_kernel<<<D2 / 256, 256>>>(g1, be1, D2);
    bn_relu_half_kernel<<<(BATCH * D2 / 4) / 256, 256>>>(Z, Ap, D2, BATCH * D2 / 4);

    // layer 2: Z = A @ W2^T    [16384, 1024], K = 2048
    gemm_f16_kernel<<<dim3(D3 / 128, BATCH / 128), 128, GEMM_SMEM>>>(Ap, W2h, Z, BATCH, D3, D2);
    bn_finalize_kernel<<<D3 / 256, 256>>>(g2, be2, D3);
    bn_relu_kernel<<<(BATCH * D3 / 4) / 256, 256>>>(Z, D3, BATCH * D3 / 4);

    // output head
    out_gemv_kernel<<<BATCH / 8, 256>>>(Z, Wout, bout, out);
}